// round 9
// baseline (speedup 1.0000x reference)
#include <cuda_runtime.h>
#include <cstdint>

// Problem constants
#define NB 2048
#define NT 64
#define NC 384
#define NH 12
#define ND 32
#define N3C 1152
#define MT 131072            // NB*NT rows
#define KDIM 384
#define SQ 50331648ull       // NB*NH*NT*ND

// ---------------- device scratch (no allocation allowed) -------------------
__device__ float g_qkv[3 * SQ];                     // (3,B,H,T,D) fp32
__device__ float g_bias[NH * NT * NT];              // (H,T,T)
__device__ float g_xt[(size_t)MT * NC];             // tf32-rounded x
__device__ float g_qwt[(size_t)N3C * NC];           // tf32-rounded qkv_w
__device__ float g_pwt[(size_t)NC * NC];            // tf32-rounded proj_w
__device__ float g_att[(size_t)MT * NC];            // attn output (tf32-rounded)

// ---------------- helpers ---------------------------------------------------
__device__ __forceinline__ uint32_t smem_u32(const void* p) {
    uint32_t a;
    asm("{ .reg .u64 t; cvta.to.shared.u64 t, %1; cvt.u32.u64 %0, t; }"
        : "=r"(a) : "l"(p));
    return a;
}
__device__ __forceinline__ float tf32r(float x) {
    uint32_t u; asm("cvt.rna.tf32.f32 %0, %1;" : "=r"(u) : "f"(x));
    return __uint_as_float(u);
}

#define CP_ASYNC16(dst, src) \
    asm volatile("cp.async.cg.shared.global [%0], [%1], 16;" \
                 :: "r"(dst), "l"(src) : "memory")
#define CP_COMMIT() asm volatile("cp.async.commit_group;" ::: "memory")
#define CP_WAIT(n)  asm volatile("cp.async.wait_group %0;" :: "n"(n) : "memory")

__device__ __forceinline__ void ldsm4(uint32_t& r0, uint32_t& r1,
                                      uint32_t& r2, uint32_t& r3, uint32_t a) {
    asm volatile("ldmatrix.sync.aligned.m8n8.x4.shared.b16 {%0,%1,%2,%3}, [%4];"
                 : "=r"(r0), "=r"(r1), "=r"(r2), "=r"(r3) : "r"(a));
}

__device__ __forceinline__ void mma_tf32(float c[4],
                                         uint32_t a0, uint32_t a1, uint32_t a2, uint32_t a3,
                                         uint32_t b0, uint32_t b1) {
    asm volatile(
        "mma.sync.aligned.m16n8k8.row.col.f32.tf32.tf32.f32 "
        "{%0,%1,%2,%3},{%4,%5,%6,%7},{%8,%9},{%0,%1,%2,%3};"
        : "+f"(c[0]), "+f"(c[1]), "+f"(c[2]), "+f"(c[3])
        : "r"(a0), "r"(a1), "r"(a2), "r"(a3), "r"(b0), "r"(b1));
}

// ---------------------------------------------------------------------------
// tf32 rounding pass (fp32 -> tf32-rounded fp32)
// ---------------------------------------------------------------------------
__global__ void round_kernel(const float* __restrict__ src,
                             float* __restrict__ dst, int n4) {
    int i = blockIdx.x * 256 + threadIdx.x;
    if (i >= n4) return;
    float4 v = ((const float4*)src)[i];
    v.x = tf32r(v.x); v.y = tf32r(v.y); v.z = tf32r(v.z); v.w = tf32r(v.w);
    ((float4*)dst)[i] = v;
}

// ---------------------------------------------------------------------------
// Bias gather
// ---------------------------------------------------------------------------
__global__ void bias_kernel(const float* __restrict__ rpb,
                            const int* __restrict__ rpi) {
    int i = blockIdx.x * 256 + threadIdx.x;
    if (i >= NH * NT * NT) return;
    int h  = i / (NT * NT);
    int qk = i - h * (NT * NT);
    g_bias[i] = rpb[rpi[qk] * NH + h];
}

// ---------------------------------------------------------------------------
// Single-pass TF32 GEMM: C[m][n] = sum_k A[m][k]*W[n][k] + bias[n]
// BM=BN=128, BK=32 fp32 (128B swizzled rows). 8 warps (2x4), warp tile 64x32.
// ldmatrix-b16 trick on fp32 quadrants. 3-stage cp.async pipeline,
// ONE __syncthreads per iteration.
// EPI==0: scatter into g_qkv with q-scale. EPI==1: write out (+bias).
// ---------------------------------------------------------------------------
#define STG 32768                // A 16KB + W 16KB per stage
#define SMT (3 * STG)            // 96 KB (3 stages)

template <int EPI>
__global__ void __launch_bounds__(256, 2)
tf_gemm(const float* __restrict__ A, const float* __restrict__ W,
        const float* __restrict__ bias, float* __restrict__ out) {
    extern __shared__ char smem[];
    const uint32_t sb = smem_u32(smem);

    const int tid  = threadIdx.x;
    const int warp = tid >> 5;
    const int lane = tid & 31;
    const int m0 = blockIdx.y * 128;
    const int n0 = blockIdx.x * 128;

    const int wm = (warp >> 2) * 64;    // 0 or 64
    const int wn = (warp & 3) * 32;     // 0,32,64,96

    // loaders: each thread cp.asyncs 4 chunks (16B) of A and of W per stage
    const int lrow = tid >> 1;
    const int lcb  = (tid & 1) * 4;
    const float* Ap = A + (size_t)(m0 + lrow) * KDIM + lcb * 4;
    const float* Wp = W + (size_t)(n0 + lrow) * KDIM + lcb * 4;
    const uint32_t lbase = lrow * 128;
    const int lsw = lrow & 7;

    auto fill = [&](int kc, int s) {
        const uint32_t base = sb + s * STG;
#pragma unroll
        for (int c = 0; c < 4; c++) {
            const uint32_t off = lbase + (((uint32_t)((lcb + c) ^ lsw)) << 4);
            CP_ASYNC16(base + off,         Ap + kc * 32 + c * 4);
            CP_ASYNC16(base + 16384 + off, Wp + kc * 32 + c * 4);
        }
    };

    float acc[4][4][4];
#pragma unroll
    for (int i = 0; i < 4; i++)
#pragma unroll
        for (int j = 0; j < 4; j++)
#pragma unroll
            for (int r = 0; r < 4; r++) acc[i][j][r] = 0.0f;

    const int mat = lane >> 3;      // 0..3
    const int mr  = lane & 7;       // 0..7

    fill(0, 0); CP_COMMIT();
    fill(1, 1); CP_COMMIT();

    int scur = 0;    // stage of kc
    int snxt = 2;    // stage of kc+2
    for (int kc = 0; kc < 12; ++kc) {
        if (kc + 2 < 12) { CP_WAIT(1); } else { CP_WAIT(0); }
        __syncthreads();                 // all warps done with compute(kc-1)
        if (kc + 2 < 12) {
            fill(kc + 2, snxt);          // overwrites stage read at kc-1: safe
            CP_COMMIT();
        }

        const uint32_t smA = sb + scur * STG;
        const uint32_t smW = smA + 16384;
        scur = (scur + 1 == 3) ? 0 : scur + 1;
        snxt = (snxt + 1 == 3) ? 0 : snxt + 1;

#pragma unroll
        for (int kg = 0; kg < 4; kg++) {   // 4 x k8 per BK=32
            uint32_t af[4][4];
            const uint32_t achunk = ((uint32_t)(kg * 2 + (mat >> 1)) ^ (uint32_t)mr) << 4;
            const uint32_t arow   = wm + ((mat & 1) << 3) + mr;
#pragma unroll
            for (int tm = 0; tm < 4; tm++) {
                const uint32_t ad = smA + (arow + tm * 16) * 128 + achunk;
                ldsm4(af[tm][0], af[tm][1], af[tm][2], af[tm][3], ad);
            }
            uint32_t bf[4][2];
            const uint32_t bchunk = ((uint32_t)(kg * 2 + (mat & 1)) ^ (uint32_t)mr) << 4;
#pragma unroll
            for (int p = 0; p < 2; p++) {
                const uint32_t brow = wn + (2 * p + (mat >> 1)) * 8 + mr;
                const uint32_t bd = smW + brow * 128 + bchunk;
                uint32_t t0, t1, t2, t3;
                ldsm4(t0, t1, t2, t3, bd);
                bf[2 * p][0] = t0; bf[2 * p][1] = t1;
                bf[2 * p + 1][0] = t2; bf[2 * p + 1][1] = t3;
            }
#pragma unroll
            for (int tm = 0; tm < 4; tm++)
#pragma unroll
                for (int tn = 0; tn < 4; tn++)
                    mma_tf32(acc[tm][tn], af[tm][0], af[tm][1], af[tm][2], af[tm][3],
                             bf[tn][0], bf[tn][1]);
        }
    }

    // epilogue: thread holds (rA, 2cA),(rA,2cA+1),(rA+8,..)
    const int rA = lane >> 2;
    const int cA = lane & 3;
#pragma unroll
    for (int tm = 0; tm < 4; tm++) {
#pragma unroll
        for (int tn = 0; tn < 4; tn++) {
#pragma unroll
            for (int half = 0; half < 2; half++) {
                const int m = m0 + wm + tm * 16 + rA + half * 8;
                const int n = n0 + wn + tn * 8 + cA * 2;
                float v0 = acc[tm][tn][half * 2 + 0] + bias[n];
                float v1 = acc[tm][tn][half * 2 + 1] + bias[n + 1];
                if (EPI == 0) {
                    const int s   = n / NC;
                    const int rem = n - s * NC;
                    const int h   = rem >> 5;
                    const int d0  = rem & 31;
                    if (s == 0) {
                        const float sc = 0.17677669529663687f;  // 1/sqrt(32)
                        v0 *= sc; v1 *= sc;
                    }
                    const int b = m >> 6;
                    const int t = m & 63;
                    float* dst = g_qkv + (size_t)s * SQ +
                                 (((size_t)(b * NH + h)) * NT + t) * ND + d0;
                    *(float2*)dst = make_float2(v0, v1);
                } else {
                    *(float2*)(out + (size_t)m * NC + n) = make_float2(v0, v1);
                }
            }
        }
    }
}

// ---------------------------------------------------------------------------
// Attention: one CTA per (b,h). Q/K/V split into tf32 hi/lo ONCE at smem
// load; mma loops are pure LDS+mma (no cvt). Pl unions over dead Q arrays.
// Writes tf32-rounded fp32 to g_att.
// ---------------------------------------------------------------------------
struct AttnSmem {
    float Kh[64][36], Kl[64][36];
    float Vh[64][36], Vl[64][36];
    union {
        struct { float Qh[64][36]; float Ql[64][36]; } q;   // 18432 B
        float Pl[64][68];                                   // 17408 B
    } u;
    float Ss[64][68];   // scores, then P_hi
};

__global__ void __launch_bounds__(256) attn_kernel() {
    extern __shared__ char asm_raw[];
    AttnSmem& S = *reinterpret_cast<AttnSmem*>(asm_raw);

    const int bh  = blockIdx.x;
    const int h   = bh % NH;
    const int tid = threadIdx.x;

    const float* Qg = g_qkv + (size_t)bh * NT * ND;
    const float* Kg = g_qkv + SQ + (size_t)bh * NT * ND;
    const float* Vg = g_qkv + 2 * SQ + (size_t)bh * NT * ND;

    // load + one-time hi/lo split
#pragma unroll
    for (int e = tid * 4; e < NT * ND; e += 1024) {
        const int t = e >> 5;
        const int d = e & 31;
        float4 q = *(const float4*)(Qg + e);
        float4 k = *(const float4*)(Kg + e);
        float4 v = *(const float4*)(Vg + e);
        float4 qh = make_float4(tf32r(q.x), tf32r(q.y), tf32r(q.z), tf32r(q.w));
        float4 kh = make_float4(tf32r(k.x), tf32r(k.y), tf32r(k.z), tf32r(k.w));
        float4 vh = make_float4(tf32r(v.x), tf32r(v.y), tf32r(v.z), tf32r(v.w));
        *(float4*)&S.u.q.Qh[t][d] = qh;
        *(float4*)&S.Kh[t][d]     = kh;
        *(float4*)&S.Vh[t][d]     = vh;
        *(float4*)&S.u.q.Ql[t][d] = make_float4(tf32r(q.x - qh.x), tf32r(q.y - qh.y),
                                                tf32r(q.z - qh.z), tf32r(q.w - qh.w));
        *(float4*)&S.Kl[t][d]     = make_float4(tf32r(k.x - kh.x), tf32r(k.y - kh.y),
                                                tf32r(k.z - kh.z), tf32r(k.w - kh.w));
        *(float4*)&S.Vl[t][d]     = make_float4(tf32r(v.x - vh.x), tf32r(v.y - vh.y),
                                                tf32r(v.z - vh.z), tf32r(v.w - vh.w));
    }
    __syncthreads();

    const int lane = tid & 31;
    const int warp = tid >> 5;
    const int rA = lane >> 2;
    const int cA = lane & 3;
    const int wm = (warp >> 1) * 16;
    const int wn = (warp & 1) * 32;

    // S = Q K^T  (3-term tf32, no cvt)
    float sc_[4][4];
#pragma unroll
    for (int i = 0; i < 4; i++)
#pragma unroll
        for (int r = 0; r < 4; r++) sc_[i][r] = 0.0f;

#pragma unroll
    for (int k0 = 0; k0 < 32; k0 += 8) {
        uint32_t ah[4], al[4];
        ah[0] = __float_as_uint(S.u.q.Qh[wm + rA][k0 + cA]);
        ah[1] = __float_as_uint(S.u.q.Qh[wm + 8 + rA][k0 + cA]);
        ah[2] = __float_as_uint(S.u.q.Qh[wm + rA][k0 + 4 + cA]);
        ah[3] = __float_as_uint(S.u.q.Qh[wm + 8 + rA][k0 + 4 + cA]);
        al[0] = __float_as_uint(S.u.q.Ql[wm + rA][k0 + cA]);
        al[1] = __float_as_uint(S.u.q.Ql[wm + 8 + rA][k0 + cA]);
        al[2] = __float_as_uint(S.u.q.Ql[wm + rA][k0 + 4 + cA]);
        al[3] = __float_as_uint(S.u.q.Ql[wm + 8 + rA][k0 + 4 + cA]);
#pragma unroll
        for (int tn = 0; tn < 4; tn++) {
            const int kr = wn + tn * 8 + rA;
            uint32_t bh0 = __float_as_uint(S.Kh[kr][k0 + cA]);
            uint32_t bh1 = __float_as_uint(S.Kh[kr][k0 + 4 + cA]);
            uint32_t bl0 = __float_as_uint(S.Kl[kr][k0 + cA]);
            uint32_t bl1 = __float_as_uint(S.Kl[kr][k0 + 4 + cA]);
            mma_tf32(sc_[tn], ah[0], ah[1], ah[2], ah[3], bh0, bh1);
            mma_tf32(sc_[tn], ah[0], ah[1], ah[2], ah[3], bl0, bl1);
            mma_tf32(sc_[tn], al[0], al[1], al[2], al[3], bh0, bh1);
        }
    }

    const float* bp = g_bias + h * NT * NT;
#pragma unroll
    for (int tn = 0; tn < 4; tn++) {
#pragma unroll
        for (int half = 0; half < 2; half++) {
            const int m = wm + rA + half * 8;
            const int n = wn + tn * 8 + cA * 2;
            float2 bz = *(const float2*)(bp + m * NT + n);
            *(float2*)&S.Ss[m][n] = make_float2(sc_[tn][half * 2 + 0] + bz.x,
                                                sc_[tn][half * 2 + 1] + bz.y);
        }
    }
    __syncthreads();   // after this, Q arrays are dead -> Pl may overwrite

    // softmax: 8 warps x 8 rows; write P hi (Ss) and P lo (Pl)
#pragma unroll
    for (int r = warp * 8; r < warp * 8 + 8; ++r) {
        float v0 = S.Ss[r][lane];
        float v1 = S.Ss[r][lane + 32];
        float mx = fmaxf(v0, v1);
#pragma unroll
        for (int o = 16; o; o >>= 1)
            mx = fmaxf(mx, __shfl_xor_sync(0xffffffffu, mx, o));
        float e0 = __expf(v0 - mx);
        float e1 = __expf(v1 - mx);
        float sm = e0 + e1;
#pragma unroll
        for (int o = 16; o; o >>= 1)
            sm += __shfl_xor_sync(0xffffffffu, sm, o);
        float inv = 1.0f / sm;
        float p0 = e0 * inv;
        float p1 = e1 * inv;
        float p0h = tf32r(p0), p1h = tf32r(p1);
        S.Ss[r][lane]        = p0h;
        S.Ss[r][lane + 32]   = p1h;
        S.u.Pl[r][lane]      = tf32r(p0 - p0h);
        S.u.Pl[r][lane + 32] = tf32r(p1 - p1h);
    }
    __syncthreads();

    // O = P V  (3-term tf32, no cvt)
    const int wn2 = (warp & 1) * 16;
    float oc[2][4];
#pragma unroll
    for (int i = 0; i < 2; i++)
#pragma unroll
        for (int r = 0; r < 4; r++) oc[i][r] = 0.0f;

#pragma unroll
    for (int k0 = 0; k0 < 64; k0 += 8) {
        uint32_t ah[4], al[4];
        ah[0] = __float_as_uint(S.Ss[wm + rA][k0 + cA]);
        ah[1] = __float_as_uint(S.Ss[wm + 8 + rA][k0 + cA]);
        ah[2] = __float_as_uint(S.Ss[wm + rA][k0 + 4 + cA]);
        ah[3] = __float_as_uint(S.Ss[wm + 8 + rA][k0 + 4 + cA]);
        al[0] = __float_as_uint(S.u.Pl[wm + rA][k0 + cA]);
        al[1] = __float_as_uint(S.u.Pl[wm + 8 + rA][k0 + cA]);
        al[2] = __float_as_uint(S.u.Pl[wm + rA][k0 + 4 + cA]);
        al[3] = __float_as_uint(S.u.Pl[wm + 8 + rA][k0 + 4 + cA]);
#pragma unroll
        for (int tn = 0; tn < 2; tn++) {
            const int dc = wn2 + tn * 8 + rA;
            uint32_t bh0 = __float_as_uint(S.Vh[k0 + cA][dc]);
            uint32_t bh1 = __float_as_uint(S.Vh[k0 + 4 + cA][dc]);
            uint32_t bl0 = __float_as_uint(S.Vl[k0 + cA][dc]);
            uint32_t bl1 = __float_as_uint(S.Vl[k0 + 4 + cA][dc]);
            mma_tf32(oc[tn], ah[0], ah[1], ah[2], ah[3], bh0, bh1);
            mma_tf32(oc[tn], ah[0], ah[1], ah[2], ah[3], bl0, bl1);
            mma_tf32(oc[tn], al[0], al[1], al[2], al[3], bh0, bh1);
        }
    }

    const int b = bh / NH;
#pragma unroll
    for (int tn = 0; tn < 2; tn++) {
#pragma unroll
        for (int half = 0; half < 2; half++) {
            const int t = wm + rA + half * 8;
            const int d = wn2 + tn * 8 + cA * 2;
            // tf32-round so the proj GEMM can run single-pass
            float2 w2 = make_float2(tf32r(oc[tn][half * 2 + 0]),
                                    tf32r(oc[tn][half * 2 + 1]));
            *(float2*)&g_att[((size_t)(b * NT + t)) * NC + h * ND + d] = w2;
        }
    }
}

// ---------------------------------------------------------------------------
// Launch  (order arranged so launch #4 = tf_gemm<0> for ncu capture)
// ---------------------------------------------------------------------------
extern "C" void kernel_launch(void* const* d_in, const int* in_sizes, int n_in,
                              void* d_out, int out_size) {
    const float* x      = (const float*)d_in[0];
    const float* qkv_w  = (const float*)d_in[1];
    const float* qkv_b  = (const float*)d_in[2];
    const float* proj_w = (const float*)d_in[3];
    const float* proj_b = (const float*)d_in[4];
    const float* rpb    = (const float*)d_in[5];
    const int*   rpi    = (const int*)d_in[6];
    float* out = (float*)d_out;

    cudaFuncSetAttribute(tf_gemm<0>, cudaFuncAttributeMaxDynamicSharedMemorySize, SMT);
    cudaFuncSetAttribute(tf_gemm<1>, cudaFuncAttributeMaxDynamicSharedMemorySize, SMT);
    cudaFuncSetAttribute(attn_kernel, cudaFuncAttributeMaxDynamicSharedMemorySize,
                         (int)sizeof(AttnSmem));

    float *xt, *qwt, *pwt, *att;
    cudaGetSymbolAddress((void**)&xt,  g_xt);
    cudaGetSymbolAddress((void**)&qwt, g_qwt);
    cudaGetSymbolAddress((void**)&pwt, g_pwt);
    cudaGetSymbolAddress((void**)&att, g_att);

    // tf32 pre-rounding (launches 1-3)
    {
        int n4 = (MT * NC) / 4;
        round_kernel<<<(n4 + 255) / 256, 256>>>(x, xt, n4);
        n4 = (N3C * NC) / 4;
        round_kernel<<<(n4 + 255) / 256, 256>>>(qkv_w, qwt, n4);
        n4 = (NC * NC) / 4;
        round_kernel<<<(n4 + 255) / 256, 256>>>(proj_w, pwt, n4);
    }

    // launch 4: the big QKV GEMM (profiled slot)
    dim3 g1(N3C / 128, MT / 128);   // (9, 1024)
    tf_gemm<0><<<g1, 256, SMT>>>(xt, qwt, qkv_b, nullptr);

    // launch 5: bias gather (only needed before attn)
    bias_kernel<<<(NH * NT * NT + 255) / 256, 256>>>(rpb, rpi);

    // launch 6: attention
    attn_kernel<<<NB * NH, 256, sizeof(AttnSmem)>>>();

    // launch 7: projection GEMM
    dim3 g2(NC / 128, MT / 128);    // (3, 1024)
    tf_gemm<1><<<g2, 256, SMT>>>(att, pwt, proj_b, out);
}

// round 10
// speedup vs baseline: 1.0315x; 1.0315x over previous
#include <cuda_runtime.h>
#include <cstdint>

// Problem constants
#define NB 2048
#define NT 64
#define NC 384
#define NH 12
#define ND 32
#define N3C 1152
#define MT 131072            // NB*NT rows
#define KDIM 384
#define SQ 50331648ull       // NB*NH*NT*ND

// ---------------- device scratch (no allocation allowed) -------------------
__device__ float g_qkv[3 * SQ];                     // (3,B,H,T,D) fp32
__device__ float g_bias[NH * NT * NT];              // (H,T,T)
__device__ float g_xt[(size_t)MT * NC];             // tf32-rounded x
__device__ float g_qwt[(size_t)N3C * NC];           // tf32-rounded qkv_w
__device__ float g_pwt[(size_t)NC * NC];            // tf32-rounded proj_w
__device__ float g_att[(size_t)MT * NC];            // attn output (tf32-rounded)

// ---------------- helpers ---------------------------------------------------
__device__ __forceinline__ uint32_t smem_u32(const void* p) {
    uint32_t a;
    asm("{ .reg .u64 t; cvta.to.shared.u64 t, %1; cvt.u32.u64 %0, t; }"
        : "=r"(a) : "l"(p));
    return a;
}
__device__ __forceinline__ float tf32r(float x) {
    uint32_t u; asm("cvt.rna.tf32.f32 %0, %1;" : "=r"(u) : "f"(x));
    return __uint_as_float(u);
}

#define CP_ASYNC16(dst, src) \
    asm volatile("cp.async.cg.shared.global [%0], [%1], 16;" \
                 :: "r"(dst), "l"(src) : "memory")
#define CP_COMMIT() asm volatile("cp.async.commit_group;" ::: "memory")
#define CP_WAIT(n)  asm volatile("cp.async.wait_group %0;" :: "n"(n) : "memory")

__device__ __forceinline__ void ldsm4(uint32_t& r0, uint32_t& r1,
                                      uint32_t& r2, uint32_t& r3, uint32_t a) {
    asm volatile("ldmatrix.sync.aligned.m8n8.x4.shared.b16 {%0,%1,%2,%3}, [%4];"
                 : "=r"(r0), "=r"(r1), "=r"(r2), "=r"(r3) : "r"(a));
}

__device__ __forceinline__ void mma_tf32(float c[4],
                                         uint32_t a0, uint32_t a1, uint32_t a2, uint32_t a3,
                                         uint32_t b0, uint32_t b1) {
    asm volatile(
        "mma.sync.aligned.m16n8k8.row.col.f32.tf32.tf32.f32 "
        "{%0,%1,%2,%3},{%4,%5,%6,%7},{%8,%9},{%0,%1,%2,%3};"
        : "+f"(c[0]), "+f"(c[1]), "+f"(c[2]), "+f"(c[3])
        : "r"(a0), "r"(a1), "r"(a2), "r"(a3), "r"(b0), "r"(b1));
}

// ---------------------------------------------------------------------------
// tf32 rounding pass (fp32 -> tf32-rounded fp32)
// ---------------------------------------------------------------------------
__global__ void round_kernel(const float* __restrict__ src,
                             float* __restrict__ dst, int n4) {
    int i = blockIdx.x * 256 + threadIdx.x;
    if (i >= n4) return;
    float4 v = ((const float4*)src)[i];
    v.x = tf32r(v.x); v.y = tf32r(v.y); v.z = tf32r(v.z); v.w = tf32r(v.w);
    ((float4*)dst)[i] = v;
}

// ---------------------------------------------------------------------------
// Bias gather
// ---------------------------------------------------------------------------
__global__ void bias_kernel(const float* __restrict__ rpb,
                            const int* __restrict__ rpi) {
    int i = blockIdx.x * 256 + threadIdx.x;
    if (i >= NH * NT * NT) return;
    int h  = i / (NT * NT);
    int qk = i - h * (NT * NT);
    g_bias[i] = rpb[rpi[qk] * NH + h];
}

// ---------------------------------------------------------------------------
// Single-pass TF32 GEMM: C[m][n] = sum_k A[m][k]*W[n][k] + bias[n]
// BM=BN=128, BK=32 fp32 (128B swizzled rows). 8 warps (2x4), warp tile 64x32.
// ldmatrix-b16 trick. 3-stage cp.async pipeline, one sync per iter.
// NEW: A-fragments double-buffered across kg so ldsm(kg+1) overlaps mma(kg).
// EPI==0: scatter into g_qkv with q-scale. EPI==1: write out (+bias).
// ---------------------------------------------------------------------------
#define STG 32768                // A 16KB + W 16KB per stage
#define SMT (3 * STG)            // 96 KB (3 stages)

template <int EPI>
__global__ void __launch_bounds__(256, 2)
tf_gemm(const float* __restrict__ A, const float* __restrict__ W,
        const float* __restrict__ bias, float* __restrict__ out) {
    extern __shared__ char smem[];
    const uint32_t sb = smem_u32(smem);

    const int tid  = threadIdx.x;
    const int warp = tid >> 5;
    const int lane = tid & 31;
    const int m0 = blockIdx.y * 128;
    const int n0 = blockIdx.x * 128;

    const int wm = (warp >> 2) * 64;    // 0 or 64
    const int wn = (warp & 3) * 32;     // 0,32,64,96

    // loaders: each thread cp.asyncs 4 chunks (16B) of A and of W per stage
    const int lrow = tid >> 1;
    const int lcb  = (tid & 1) * 4;
    const float* Ap = A + (size_t)(m0 + lrow) * KDIM + lcb * 4;
    const float* Wp = W + (size_t)(n0 + lrow) * KDIM + lcb * 4;
    const uint32_t lbase = lrow * 128;
    const int lsw = lrow & 7;

    auto fill = [&](int kc, int s) {
        const uint32_t base = sb + s * STG;
#pragma unroll
        for (int c = 0; c < 4; c++) {
            const uint32_t off = lbase + (((uint32_t)((lcb + c) ^ lsw)) << 4);
            CP_ASYNC16(base + off,         Ap + kc * 32 + c * 4);
            CP_ASYNC16(base + 16384 + off, Wp + kc * 32 + c * 4);
        }
    };

    float acc[4][4][4];
#pragma unroll
    for (int i = 0; i < 4; i++)
#pragma unroll
        for (int j = 0; j < 4; j++)
#pragma unroll
            for (int r = 0; r < 4; r++) acc[i][j][r] = 0.0f;

    const int mat = lane >> 3;      // 0..3
    const int mr  = lane & 7;       // 0..7

    // per-warp fragment addressing
    const uint32_t arow = wm + ((mat & 1) << 3) + mr;

    fill(0, 0); CP_COMMIT();
    fill(1, 1); CP_COMMIT();

    int scur = 0;    // stage of kc
    int snxt = 2;    // stage of kc+2
    for (int kc = 0; kc < 12; ++kc) {
        if (kc + 2 < 12) { CP_WAIT(1); } else { CP_WAIT(0); }
        __syncthreads();                 // all warps done with compute(kc-1)
        if (kc + 2 < 12) {
            fill(kc + 2, snxt);          // overwrites stage read at kc-1: safe
            CP_COMMIT();
        }

        const uint32_t smA = sb + scur * STG;
        const uint32_t smW = smA + 16384;
        scur = (scur + 1 == 3) ? 0 : scur + 1;
        snxt = (snxt + 1 == 3) ? 0 : snxt + 1;

        // A-fragment double buffer across kg
        uint32_t afA[4][4], afB[4][4];
        {
            const uint32_t achunk = ((uint32_t)(0 + (mat >> 1)) ^ (uint32_t)mr) << 4;
#pragma unroll
            for (int tm = 0; tm < 4; tm++) {
                const uint32_t ad = smA + (arow + tm * 16) * 128 + achunk;
                ldsm4(afA[tm][0], afA[tm][1], afA[tm][2], afA[tm][3], ad);
            }
        }

#pragma unroll
        for (int kg = 0; kg < 4; kg++) {   // 4 x k8 per BK=32
            uint32_t (*cur)[4] = (kg & 1) ? afB : afA;
            uint32_t (*nxt)[4] = (kg & 1) ? afA : afB;
            if (kg < 3) {
                const uint32_t achunk =
                    ((uint32_t)((kg + 1) * 2 + (mat >> 1)) ^ (uint32_t)mr) << 4;
#pragma unroll
                for (int tm = 0; tm < 4; tm++) {
                    const uint32_t ad = smA + (arow + tm * 16) * 128 + achunk;
                    ldsm4(nxt[tm][0], nxt[tm][1], nxt[tm][2], nxt[tm][3], ad);
                }
            }
            uint32_t bf[4][2];
            const uint32_t bchunk = ((uint32_t)(kg * 2 + (mat & 1)) ^ (uint32_t)mr) << 4;
#pragma unroll
            for (int p = 0; p < 2; p++) {
                const uint32_t brow = wn + (2 * p + (mat >> 1)) * 8 + mr;
                const uint32_t bd = smW + brow * 128 + bchunk;
                uint32_t t0, t1, t2, t3;
                ldsm4(t0, t1, t2, t3, bd);
                bf[2 * p][0] = t0; bf[2 * p][1] = t1;
                bf[2 * p + 1][0] = t2; bf[2 * p + 1][1] = t3;
            }
#pragma unroll
            for (int tm = 0; tm < 4; tm++)
#pragma unroll
                for (int tn = 0; tn < 4; tn++)
                    mma_tf32(acc[tm][tn], cur[tm][0], cur[tm][1], cur[tm][2], cur[tm][3],
                             bf[tn][0], bf[tn][1]);
        }
    }

    // epilogue: thread holds (rA, 2cA),(rA,2cA+1),(rA+8,..)
    const int rA = lane >> 2;
    const int cA = lane & 3;
#pragma unroll
    for (int tm = 0; tm < 4; tm++) {
#pragma unroll
        for (int tn = 0; tn < 4; tn++) {
#pragma unroll
            for (int half = 0; half < 2; half++) {
                const int m = m0 + wm + tm * 16 + rA + half * 8;
                const int n = n0 + wn + tn * 8 + cA * 2;
                float v0 = acc[tm][tn][half * 2 + 0] + bias[n];
                float v1 = acc[tm][tn][half * 2 + 1] + bias[n + 1];
                if (EPI == 0) {
                    const int s   = n / NC;
                    const int rem = n - s * NC;
                    const int h   = rem >> 5;
                    const int d0  = rem & 31;
                    if (s == 0) {
                        const float sc = 0.17677669529663687f;  // 1/sqrt(32)
                        v0 *= sc; v1 *= sc;
                    }
                    const int b = m >> 6;
                    const int t = m & 63;
                    float* dst = g_qkv + (size_t)s * SQ +
                                 (((size_t)(b * NH + h)) * NT + t) * ND + d0;
                    *(float2*)dst = make_float2(v0, v1);
                } else {
                    *(float2*)(out + (size_t)m * NC + n) = make_float2(v0, v1);
                }
            }
        }
    }
}

// ---------------------------------------------------------------------------
// Attention: one CTA per (b,h). 3xTF32 for QK^T and PV.  (R8 version)
// Writes tf32-rounded fp32 to g_att.
// ---------------------------------------------------------------------------
__global__ void __launch_bounds__(256) attn_kernel() {
    __shared__ float Qs[64][36];
    __shared__ float Ks[64][36];
    __shared__ float Vs[64][36];
    __shared__ float Ss[64][68];

    const int bh  = blockIdx.x;
    const int h   = bh % NH;
    const int tid = threadIdx.x;

    const float* Qg = g_qkv + (size_t)bh * NT * ND;
    const float* Kg = g_qkv + SQ + (size_t)bh * NT * ND;
    const float* Vg = g_qkv + 2 * SQ + (size_t)bh * NT * ND;

#pragma unroll
    for (int e = tid * 4; e < NT * ND; e += 1024) {
        const int t = e >> 5;
        const int d = e & 31;
        *(float4*)&Qs[t][d] = *(const float4*)(Qg + e);
        *(float4*)&Ks[t][d] = *(const float4*)(Kg + e);
        *(float4*)&Vs[t][d] = *(const float4*)(Vg + e);
    }
    __syncthreads();

    const int lane = tid & 31;
    const int warp = tid >> 5;
    const int rA = lane >> 2;
    const int cA = lane & 3;
    const int wm = (warp >> 1) * 16;
    const int wn = (warp & 1) * 32;

    // S = Q K^T (3xTF32)
    float sc_[4][4];
#pragma unroll
    for (int i = 0; i < 4; i++)
#pragma unroll
        for (int r = 0; r < 4; r++) sc_[i][r] = 0.0f;

#pragma unroll
    for (int k0 = 0; k0 < 32; k0 += 8) {
        float a[4];
        a[0] = Qs[wm + rA][k0 + cA];
        a[1] = Qs[wm + 8 + rA][k0 + cA];
        a[2] = Qs[wm + rA][k0 + 4 + cA];
        a[3] = Qs[wm + 8 + rA][k0 + 4 + cA];
        uint32_t ah[4], al[4];
#pragma unroll
        for (int i = 0; i < 4; i++) {
            float hv = tf32r(a[i]);
            ah[i] = __float_as_uint(hv);
            al[i] = __float_as_uint(tf32r(a[i] - hv));
        }
#pragma unroll
        for (int tn = 0; tn < 4; tn++) {
            float b0 = Ks[wn + tn * 8 + rA][k0 + cA];
            float b1 = Ks[wn + tn * 8 + rA][k0 + 4 + cA];
            float bh0 = tf32r(b0), bh1 = tf32r(b1);
            uint32_t ubh0 = __float_as_uint(bh0), ubh1 = __float_as_uint(bh1);
            uint32_t ubl0 = __float_as_uint(tf32r(b0 - bh0));
            uint32_t ubl1 = __float_as_uint(tf32r(b1 - bh1));
            mma_tf32(sc_[tn], ah[0], ah[1], ah[2], ah[3], ubh0, ubh1);
            mma_tf32(sc_[tn], ah[0], ah[1], ah[2], ah[3], ubl0, ubl1);
            mma_tf32(sc_[tn], al[0], al[1], al[2], al[3], ubh0, ubh1);
        }
    }

    const float* bp = g_bias + h * NT * NT;
#pragma unroll
    for (int tn = 0; tn < 4; tn++) {
#pragma unroll
        for (int half = 0; half < 2; half++) {
            const int m = wm + rA + half * 8;
            const int n = wn + tn * 8 + cA * 2;
            float2 bz = *(const float2*)(bp + m * NT + n);
            *(float2*)&Ss[m][n] = make_float2(sc_[tn][half * 2 + 0] + bz.x,
                                              sc_[tn][half * 2 + 1] + bz.y);
        }
    }
    __syncthreads();

    // softmax: 8 warps x 8 rows
#pragma unroll
    for (int r = warp * 8; r < warp * 8 + 8; ++r) {
        float v0 = Ss[r][lane];
        float v1 = Ss[r][lane + 32];
        float mx = fmaxf(v0, v1);
#pragma unroll
        for (int o = 16; o; o >>= 1)
            mx = fmaxf(mx, __shfl_xor_sync(0xffffffffu, mx, o));
        float e0 = __expf(v0 - mx);
        float e1 = __expf(v1 - mx);
        float sm = e0 + e1;
#pragma unroll
        for (int o = 16; o; o >>= 1)
            sm += __shfl_xor_sync(0xffffffffu, sm, o);
        float inv = 1.0f / sm;
        Ss[r][lane]      = e0 * inv;
        Ss[r][lane + 32] = e1 * inv;
    }
    __syncthreads();

    // O = P V (3xTF32)
    const int wn2 = (warp & 1) * 16;
    float oc[2][4];
#pragma unroll
    for (int i = 0; i < 2; i++)
#pragma unroll
        for (int r = 0; r < 4; r++) oc[i][r] = 0.0f;

#pragma unroll
    for (int k0 = 0; k0 < 64; k0 += 8) {
        float a[4];
        a[0] = Ss[wm + rA][k0 + cA];
        a[1] = Ss[wm + 8 + rA][k0 + cA];
        a[2] = Ss[wm + rA][k0 + 4 + cA];
        a[3] = Ss[wm + 8 + rA][k0 + 4 + cA];
        uint32_t ah[4], al[4];
#pragma unroll
        for (int i = 0; i < 4; i++) {
            float hv = tf32r(a[i]);
            ah[i] = __float_as_uint(hv);
            al[i] = __float_as_uint(tf32r(a[i] - hv));
        }
#pragma unroll
        for (int tn = 0; tn < 2; tn++) {
            float b0 = Vs[k0 + cA][wn2 + tn * 8 + rA];
            float b1 = Vs[k0 + 4 + cA][wn2 + tn * 8 + rA];
            float bh0 = tf32r(b0), bh1 = tf32r(b1);
            uint32_t ubh0 = __float_as_uint(bh0), ubh1 = __float_as_uint(bh1);
            uint32_t ubl0 = __float_as_uint(tf32r(b0 - bh0));
            uint32_t ubl1 = __float_as_uint(tf32r(b1 - bh1));
            mma_tf32(oc[tn], ah[0], ah[1], ah[2], ah[3], ubh0, ubh1);
            mma_tf32(oc[tn], ah[0], ah[1], ah[2], ah[3], ubl0, ubl1);
            mma_tf32(oc[tn], al[0], al[1], al[2], al[3], ubh0, ubh1);
        }
    }

    const int b = bh / NH;
#pragma unroll
    for (int tn = 0; tn < 2; tn++) {
#pragma unroll
        for (int half = 0; half < 2; half++) {
            const int t = wm + rA + half * 8;
            const int d = wn2 + tn * 8 + cA * 2;
            // tf32-round so the proj GEMM can run single-pass
            float2 w2 = make_float2(tf32r(oc[tn][half * 2 + 0]),
                                    tf32r(oc[tn][half * 2 + 1]));
            *(float2*)&g_att[((size_t)(b * NT + t)) * NC + h * ND + d] = w2;
        }
    }
}

// ---------------------------------------------------------------------------
// Launch  (order arranged so launch #4 = tf_gemm<0> for ncu capture)
// ---------------------------------------------------------------------------
extern "C" void kernel_launch(void* const* d_in, const int* in_sizes, int n_in,
                              void* d_out, int out_size) {
    const float* x      = (const float*)d_in[0];
    const float* qkv_w  = (const float*)d_in[1];
    const float* qkv_b  = (const float*)d_in[2];
    const float* proj_w = (const float*)d_in[3];
    const float* proj_b = (const float*)d_in[4];
    const float* rpb    = (const float*)d_in[5];
    const int*   rpi    = (const int*)d_in[6];
    float* out = (float*)d_out;

    cudaFuncSetAttribute(tf_gemm<0>, cudaFuncAttributeMaxDynamicSharedMemorySize, SMT);
    cudaFuncSetAttribute(tf_gemm<1>, cudaFuncAttributeMaxDynamicSharedMemorySize, SMT);

    float *xt, *qwt, *pwt, *att;
    cudaGetSymbolAddress((void**)&xt,  g_xt);
    cudaGetSymbolAddress((void**)&qwt, g_qwt);
    cudaGetSymbolAddress((void**)&pwt, g_pwt);
    cudaGetSymbolAddress((void**)&att, g_att);

    // tf32 pre-rounding (launches 1-3)
    {
        int n4 = (MT * NC) / 4;
        round_kernel<<<(n4 + 255) / 256, 256>>>(x, xt, n4);
        n4 = (N3C * NC) / 4;
        round_kernel<<<(n4 + 255) / 256, 256>>>(qkv_w, qwt, n4);
        n4 = (NC * NC) / 4;
        round_kernel<<<(n4 + 255) / 256, 256>>>(proj_w, pwt, n4);
    }

    // launch 4: the big QKV GEMM (profiled slot)
    dim3 g1(N3C / 128, MT / 128);   // (9, 1024)
    tf_gemm<0><<<g1, 256, SMT>>>(xt, qwt, qkv_b, nullptr);

    // launch 5: bias gather (only needed before attn)
    bias_kernel<<<(NH * NT * NT + 255) / 256, 256>>>(rpb, rpi);

    // launch 6: attention
    attn_kernel<<<NB * NH, 256>>>();

    // launch 7: projection GEMM
    dim3 g2(NC / 128, MT / 128);    // (3, 1024)
    tf_gemm<1><<<g2, 256, SMT>>>(att, pwt, proj_b, out);
}

// round 11
// speedup vs baseline: 1.1055x; 1.0718x over previous
#include <cuda_runtime.h>
#include <cstdint>

// Problem constants
#define NB 2048
#define NT 64
#define NC 384
#define NH 12
#define ND 32
#define N3C 1152
#define MT 131072            // NB*NT rows
#define KDIM 384
#define SQ 50331648ull       // NB*NH*NT*ND

// ---------------- device scratch (no allocation allowed) -------------------
__device__ float g_qkv[3 * SQ];                     // (3,B,H,T,D) tf32-valued fp32
__device__ float g_bias[NH * NT * NT];              // (H,T,T)
__device__ float g_xt[(size_t)MT * NC];             // tf32-rounded x
__device__ float g_qwt[(size_t)N3C * NC];           // tf32-rounded qkv_w
__device__ float g_pwt[(size_t)NC * NC];            // tf32-rounded proj_w
__device__ float g_att[(size_t)MT * NC];            // attn output (tf32-rounded)

// ---------------- helpers ---------------------------------------------------
__device__ __forceinline__ uint32_t smem_u32(const void* p) {
    uint32_t a;
    asm("{ .reg .u64 t; cvta.to.shared.u64 t, %1; cvt.u32.u64 %0, t; }"
        : "=r"(a) : "l"(p));
    return a;
}
__device__ __forceinline__ float tf32r(float x) {
    uint32_t u; asm("cvt.rna.tf32.f32 %0, %1;" : "=r"(u) : "f"(x));
    return __uint_as_float(u);
}

#define CP_ASYNC16(dst, src) \
    asm volatile("cp.async.cg.shared.global [%0], [%1], 16;" \
                 :: "r"(dst), "l"(src) : "memory")
#define CP_COMMIT() asm volatile("cp.async.commit_group;" ::: "memory")
#define CP_WAIT(n)  asm volatile("cp.async.wait_group %0;" :: "n"(n) : "memory")

__device__ __forceinline__ void ldsm4(uint32_t& r0, uint32_t& r1,
                                      uint32_t& r2, uint32_t& r3, uint32_t a) {
    asm volatile("ldmatrix.sync.aligned.m8n8.x4.shared.b16 {%0,%1,%2,%3}, [%4];"
                 : "=r"(r0), "=r"(r1), "=r"(r2), "=r"(r3) : "r"(a));
}

__device__ __forceinline__ void mma_tf32(float c[4],
                                         uint32_t a0, uint32_t a1, uint32_t a2, uint32_t a3,
                                         uint32_t b0, uint32_t b1) {
    asm volatile(
        "mma.sync.aligned.m16n8k8.row.col.f32.tf32.tf32.f32 "
        "{%0,%1,%2,%3},{%4,%5,%6,%7},{%8,%9},{%0,%1,%2,%3};"
        : "+f"(c[0]), "+f"(c[1]), "+f"(c[2]), "+f"(c[3])
        : "r"(a0), "r"(a1), "r"(a2), "r"(a3), "r"(b0), "r"(b1));
}

// ---------------------------------------------------------------------------
// tf32 rounding pass (fp32 -> tf32-rounded fp32)
// ---------------------------------------------------------------------------
__global__ void round_kernel(const float* __restrict__ src,
                             float* __restrict__ dst, int n4) {
    int i = blockIdx.x * 256 + threadIdx.x;
    if (i >= n4) return;
    float4 v = ((const float4*)src)[i];
    v.x = tf32r(v.x); v.y = tf32r(v.y); v.z = tf32r(v.z); v.w = tf32r(v.w);
    ((float4*)dst)[i] = v;
}

// ---------------------------------------------------------------------------
// Bias gather
// ---------------------------------------------------------------------------
__global__ void bias_kernel(const float* __restrict__ rpb,
                            const int* __restrict__ rpi) {
    int i = blockIdx.x * 256 + threadIdx.x;
    if (i >= NH * NT * NT) return;
    int h  = i / (NT * NT);
    int qk = i - h * (NT * NT);
    g_bias[i] = rpb[rpi[qk] * NH + h];
}

// ---------------------------------------------------------------------------
// Single-pass TF32 GEMM: C[m][n] = sum_k A[m][k]*W[n][k] + bias[n]
// BM=BN=128, BK=32 fp32 (128B swizzled rows). 8 warps (2x4), warp tile 64x32.
// ldmatrix-b16 trick on fp32 quadrants. 3-stage cp.async pipeline,
// ONE __syncthreads per iteration.  (R8 version — proven best)
// EPI==0: scatter tf32-ROUNDED values into g_qkv with q-scale.
// EPI==1: write out (+bias).
// ---------------------------------------------------------------------------
#define STG 32768                // A 16KB + W 16KB per stage
#define SMT (3 * STG)            // 96 KB (3 stages)

template <int EPI>
__global__ void __launch_bounds__(256, 2)
tf_gemm(const float* __restrict__ A, const float* __restrict__ W,
        const float* __restrict__ bias, float* __restrict__ out) {
    extern __shared__ char smem[];
    const uint32_t sb = smem_u32(smem);

    const int tid  = threadIdx.x;
    const int warp = tid >> 5;
    const int lane = tid & 31;
    const int m0 = blockIdx.y * 128;
    const int n0 = blockIdx.x * 128;

    const int wm = (warp >> 2) * 64;    // 0 or 64
    const int wn = (warp & 3) * 32;     // 0,32,64,96

    // loaders: each thread cp.asyncs 4 chunks (16B) of A and of W per stage
    const int lrow = tid >> 1;
    const int lcb  = (tid & 1) * 4;
    const float* Ap = A + (size_t)(m0 + lrow) * KDIM + lcb * 4;
    const float* Wp = W + (size_t)(n0 + lrow) * KDIM + lcb * 4;
    const uint32_t lbase = lrow * 128;
    const int lsw = lrow & 7;

    auto fill = [&](int kc, int s) {
        const uint32_t base = sb + s * STG;
#pragma unroll
        for (int c = 0; c < 4; c++) {
            const uint32_t off = lbase + (((uint32_t)((lcb + c) ^ lsw)) << 4);
            CP_ASYNC16(base + off,         Ap + kc * 32 + c * 4);
            CP_ASYNC16(base + 16384 + off, Wp + kc * 32 + c * 4);
        }
    };

    float acc[4][4][4];
#pragma unroll
    for (int i = 0; i < 4; i++)
#pragma unroll
        for (int j = 0; j < 4; j++)
#pragma unroll
            for (int r = 0; r < 4; r++) acc[i][j][r] = 0.0f;

    const int mat = lane >> 3;      // 0..3
    const int mr  = lane & 7;       // 0..7

    fill(0, 0); CP_COMMIT();
    fill(1, 1); CP_COMMIT();

    int scur = 0;    // stage of kc
    int snxt = 2;    // stage of kc+2
    for (int kc = 0; kc < 12; ++kc) {
        if (kc + 2 < 12) { CP_WAIT(1); } else { CP_WAIT(0); }
        __syncthreads();                 // all warps done with compute(kc-1)
        if (kc + 2 < 12) {
            fill(kc + 2, snxt);          // overwrites stage read at kc-1: safe
            CP_COMMIT();
        }

        const uint32_t smA = sb + scur * STG;
        const uint32_t smW = smA + 16384;
        scur = (scur + 1 == 3) ? 0 : scur + 1;
        snxt = (snxt + 1 == 3) ? 0 : snxt + 1;

#pragma unroll
        for (int kg = 0; kg < 4; kg++) {   // 4 x k8 per BK=32
            uint32_t af[4][4];
            const uint32_t achunk = ((uint32_t)(kg * 2 + (mat >> 1)) ^ (uint32_t)mr) << 4;
            const uint32_t arow   = wm + ((mat & 1) << 3) + mr;
#pragma unroll
            for (int tm = 0; tm < 4; tm++) {
                const uint32_t ad = smA + (arow + tm * 16) * 128 + achunk;
                ldsm4(af[tm][0], af[tm][1], af[tm][2], af[tm][3], ad);
            }
            uint32_t bf[4][2];
            const uint32_t bchunk = ((uint32_t)(kg * 2 + (mat & 1)) ^ (uint32_t)mr) << 4;
#pragma unroll
            for (int p = 0; p < 2; p++) {
                const uint32_t brow = wn + (2 * p + (mat >> 1)) * 8 + mr;
                const uint32_t bd = smW + brow * 128 + bchunk;
                uint32_t t0, t1, t2, t3;
                ldsm4(t0, t1, t2, t3, bd);
                bf[2 * p][0] = t0; bf[2 * p][1] = t1;
                bf[2 * p + 1][0] = t2; bf[2 * p + 1][1] = t3;
            }
#pragma unroll
            for (int tm = 0; tm < 4; tm++)
#pragma unroll
                for (int tn = 0; tn < 4; tn++)
                    mma_tf32(acc[tm][tn], af[tm][0], af[tm][1], af[tm][2], af[tm][3],
                             bf[tn][0], bf[tn][1]);
        }
    }

    // epilogue: thread holds (rA, 2cA),(rA,2cA+1),(rA+8,..)
    const int rA = lane >> 2;
    const int cA = lane & 3;
#pragma unroll
    for (int tm = 0; tm < 4; tm++) {
#pragma unroll
        for (int tn = 0; tn < 4; tn++) {
#pragma unroll
            for (int half = 0; half < 2; half++) {
                const int m = m0 + wm + tm * 16 + rA + half * 8;
                const int n = n0 + wn + tn * 8 + cA * 2;
                float v0 = acc[tm][tn][half * 2 + 0] + bias[n];
                float v1 = acc[tm][tn][half * 2 + 1] + bias[n + 1];
                if (EPI == 0) {
                    const int s   = n / NC;
                    const int rem = n - s * NC;
                    const int h   = rem >> 5;
                    const int d0  = rem & 31;
                    if (s == 0) {
                        const float sc = 0.17677669529663687f;  // 1/sqrt(32)
                        v0 *= sc; v1 *= sc;
                    }
                    const int b = m >> 6;
                    const int t = m & 63;
                    float* dst = g_qkv + (size_t)s * SQ +
                                 (((size_t)(b * NH + h)) * NT + t) * ND + d0;
                    // tf32-round here so attention needs ZERO cvt
                    *(float2*)dst = make_float2(tf32r(v0), tf32r(v1));
                } else {
                    *(float2*)(out + (size_t)m * NC + n) = make_float2(v0, v1);
                }
            }
        }
    }
}

// ---------------------------------------------------------------------------
// Attention: one CTA per (b,h). SINGLE-PASS tf32 for QK^T and PV —
// inputs arrive tf32-valued from the GEMM epilogue; softmax emits tf32r(P).
// (error profile empirically validated in Round 2: rel_err 7.0e-4)
// Writes tf32-rounded fp32 to g_att.
// ---------------------------------------------------------------------------
__global__ void __launch_bounds__(256) attn_kernel() {
    __shared__ float Qs[64][36];
    __shared__ float Ks[64][36];
    __shared__ float Vs[64][36];
    __shared__ float Ss[64][68];

    const int bh  = blockIdx.x;
    const int h   = bh % NH;
    const int tid = threadIdx.x;

    const float* Qg = g_qkv + (size_t)bh * NT * ND;
    const float* Kg = g_qkv + SQ + (size_t)bh * NT * ND;
    const float* Vg = g_qkv + 2 * SQ + (size_t)bh * NT * ND;

#pragma unroll
    for (int e = tid * 4; e < NT * ND; e += 1024) {
        const int t = e >> 5;
        const int d = e & 31;
        *(float4*)&Qs[t][d] = *(const float4*)(Qg + e);
        *(float4*)&Ks[t][d] = *(const float4*)(Kg + e);
        *(float4*)&Vs[t][d] = *(const float4*)(Vg + e);
    }
    __syncthreads();

    const int lane = tid & 31;
    const int warp = tid >> 5;
    const int rA = lane >> 2;
    const int cA = lane & 3;
    const int wm = (warp >> 1) * 16;
    const int wn = (warp & 1) * 32;

    // S = Q K^T (single-pass tf32; operands already tf32-valued)
    float sc_[4][4];
#pragma unroll
    for (int i = 0; i < 4; i++)
#pragma unroll
        for (int r = 0; r < 4; r++) sc_[i][r] = 0.0f;

#pragma unroll
    for (int k0 = 0; k0 < 32; k0 += 8) {
        uint32_t a0 = __float_as_uint(Qs[wm + rA][k0 + cA]);
        uint32_t a1 = __float_as_uint(Qs[wm + 8 + rA][k0 + cA]);
        uint32_t a2 = __float_as_uint(Qs[wm + rA][k0 + 4 + cA]);
        uint32_t a3 = __float_as_uint(Qs[wm + 8 + rA][k0 + 4 + cA]);
#pragma unroll
        for (int tn = 0; tn < 4; tn++) {
            const int kr = wn + tn * 8 + rA;
            uint32_t b0 = __float_as_uint(Ks[kr][k0 + cA]);
            uint32_t b1 = __float_as_uint(Ks[kr][k0 + 4 + cA]);
            mma_tf32(sc_[tn], a0, a1, a2, a3, b0, b1);
        }
    }

    const float* bp = g_bias + h * NT * NT;
#pragma unroll
    for (int tn = 0; tn < 4; tn++) {
#pragma unroll
        for (int half = 0; half < 2; half++) {
            const int m = wm + rA + half * 8;
            const int n = wn + tn * 8 + cA * 2;
            float2 bz = *(const float2*)(bp + m * NT + n);
            *(float2*)&Ss[m][n] = make_float2(sc_[tn][half * 2 + 0] + bz.x,
                                              sc_[tn][half * 2 + 1] + bz.y);
        }
    }
    __syncthreads();

    // softmax: 8 warps x 8 rows; emit tf32-rounded probabilities
#pragma unroll
    for (int r = warp * 8; r < warp * 8 + 8; ++r) {
        float v0 = Ss[r][lane];
        float v1 = Ss[r][lane + 32];
        float mx = fmaxf(v0, v1);
#pragma unroll
        for (int o = 16; o; o >>= 1)
            mx = fmaxf(mx, __shfl_xor_sync(0xffffffffu, mx, o));
        float e0 = __expf(v0 - mx);
        float e1 = __expf(v1 - mx);
        float sm = e0 + e1;
#pragma unroll
        for (int o = 16; o; o >>= 1)
            sm += __shfl_xor_sync(0xffffffffu, sm, o);
        float inv = 1.0f / sm;
        Ss[r][lane]      = tf32r(e0 * inv);
        Ss[r][lane + 32] = tf32r(e1 * inv);
    }
    __syncthreads();

    // O = P V (single-pass tf32)
    const int wn2 = (warp & 1) * 16;
    float oc[2][4];
#pragma unroll
    for (int i = 0; i < 2; i++)
#pragma unroll
        for (int r = 0; r < 4; r++) oc[i][r] = 0.0f;

#pragma unroll
    for (int k0 = 0; k0 < 64; k0 += 8) {
        uint32_t a0 = __float_as_uint(Ss[wm + rA][k0 + cA]);
        uint32_t a1 = __float_as_uint(Ss[wm + 8 + rA][k0 + cA]);
        uint32_t a2 = __float_as_uint(Ss[wm + rA][k0 + 4 + cA]);
        uint32_t a3 = __float_as_uint(Ss[wm + 8 + rA][k0 + 4 + cA]);
#pragma unroll
        for (int tn = 0; tn < 2; tn++) {
            const int dc = wn2 + tn * 8 + rA;
            uint32_t b0 = __float_as_uint(Vs[k0 + cA][dc]);
            uint32_t b1 = __float_as_uint(Vs[k0 + 4 + cA][dc]);
            mma_tf32(oc[tn], a0, a1, a2, a3, b0, b1);
        }
    }

    const int b = bh / NH;
#pragma unroll
    for (int tn = 0; tn < 2; tn++) {
#pragma unroll
        for (int half = 0; half < 2; half++) {
            const int t = wm + rA + half * 8;
            const int d = wn2 + tn * 8 + cA * 2;
            // tf32-round so the proj GEMM can run single-pass
            float2 w2 = make_float2(tf32r(oc[tn][half * 2 + 0]),
                                    tf32r(oc[tn][half * 2 + 1]));
            *(float2*)&g_att[((size_t)(b * NT + t)) * NC + h * ND + d] = w2;
        }
    }
}

// ---------------------------------------------------------------------------
// Launch  (order arranged so launch #4 = tf_gemm<0> for ncu capture)
// ---------------------------------------------------------------------------
extern "C" void kernel_launch(void* const* d_in, const int* in_sizes, int n_in,
                              void* d_out, int out_size) {
    const float* x      = (const float*)d_in[0];
    const float* qkv_w  = (const float*)d_in[1];
    const float* qkv_b  = (const float*)d_in[2];
    const float* proj_w = (const float*)d_in[3];
    const float* proj_b = (const float*)d_in[4];
    const float* rpb    = (const float*)d_in[5];
    const int*   rpi    = (const int*)d_in[6];
    float* out = (float*)d_out;

    cudaFuncSetAttribute(tf_gemm<0>, cudaFuncAttributeMaxDynamicSharedMemorySize, SMT);
    cudaFuncSetAttribute(tf_gemm<1>, cudaFuncAttributeMaxDynamicSharedMemorySize, SMT);

    float *xt, *qwt, *pwt, *att;
    cudaGetSymbolAddress((void**)&xt,  g_xt);
    cudaGetSymbolAddress((void**)&qwt, g_qwt);
    cudaGetSymbolAddress((void**)&pwt, g_pwt);
    cudaGetSymbolAddress((void**)&att, g_att);

    // tf32 pre-rounding (launches 1-3)
    {
        int n4 = (MT * NC) / 4;
        round_kernel<<<(n4 + 255) / 256, 256>>>(x, xt, n4);
        n4 = (N3C * NC) / 4;
        round_kernel<<<(n4 + 255) / 256, 256>>>(qkv_w, qwt, n4);
        n4 = (NC * NC) / 4;
        round_kernel<<<(n4 + 255) / 256, 256>>>(proj_w, pwt, n4);
    }

    // launch 4: the big QKV GEMM (profiled slot)
    dim3 g1(N3C / 128, MT / 128);   // (9, 1024)
    tf_gemm<0><<<g1, 256, SMT>>>(xt, qwt, qkv_b, nullptr);

    // launch 5: bias gather (only needed before attn)
    bias_kernel<<<(NH * NT * NT + 255) / 256, 256>>>(rpb, rpi);

    // launch 6: attention
    attn_kernel<<<NB * NH, 256>>>();

    // launch 7: projection GEMM
    dim3 g2(NC / 128, MT / 128);    // (3, 1024)
    tf_gemm<1><<<g2, 256, SMT>>>(att, pwt, proj_b, out);
}

// round 12
// speedup vs baseline: 1.1283x; 1.0206x over previous
#include <cuda_runtime.h>
#include <cstdint>

// Problem constants
#define NB 2048
#define NT 64
#define NC 384
#define NH 12
#define ND 32
#define N3C 1152
#define MT 131072            // NB*NT rows
#define KDIM 384
#define SQ 50331648ull       // NB*NH*NT*ND

// ---------------- device scratch (no allocation allowed) -------------------
__device__ float g_qkv[3 * SQ];                     // (3,B,H,T,D) tf32-valued fp32
__device__ float g_bias[NH * NT * NT];              // (H,T,T)
__device__ float g_xt[(size_t)MT * NC];             // tf32-rounded x
__device__ float g_qwt[(size_t)N3C * NC];           // tf32-rounded qkv_w
__device__ float g_pwt[(size_t)NC * NC];            // tf32-rounded proj_w
__device__ float g_att[(size_t)MT * NC];            // attn output (tf32-rounded)

// ---------------- helpers ---------------------------------------------------
__device__ __forceinline__ uint32_t smem_u32(const void* p) {
    uint32_t a;
    asm("{ .reg .u64 t; cvta.to.shared.u64 t, %1; cvt.u32.u64 %0, t; }"
        : "=r"(a) : "l"(p));
    return a;
}
__device__ __forceinline__ float tf32r(float x) {
    uint32_t u; asm("cvt.rna.tf32.f32 %0, %1;" : "=r"(u) : "f"(x));
    return __uint_as_float(u);
}

#define CP_ASYNC16(dst, src) \
    asm volatile("cp.async.cg.shared.global [%0], [%1], 16;" \
                 :: "r"(dst), "l"(src) : "memory")
#define CP_COMMIT() asm volatile("cp.async.commit_group;" ::: "memory")
#define CP_WAIT(n)  asm volatile("cp.async.wait_group %0;" :: "n"(n) : "memory")

__device__ __forceinline__ void ldsm4(uint32_t& r0, uint32_t& r1,
                                      uint32_t& r2, uint32_t& r3, uint32_t a) {
    asm volatile("ldmatrix.sync.aligned.m8n8.x4.shared.b16 {%0,%1,%2,%3}, [%4];"
                 : "=r"(r0), "=r"(r1), "=r"(r2), "=r"(r3) : "r"(a));
}

__device__ __forceinline__ void mma_tf32(float c[4],
                                         uint32_t a0, uint32_t a1, uint32_t a2, uint32_t a3,
                                         uint32_t b0, uint32_t b1) {
    asm volatile(
        "mma.sync.aligned.m16n8k8.row.col.f32.tf32.tf32.f32 "
        "{%0,%1,%2,%3},{%4,%5,%6,%7},{%8,%9},{%0,%1,%2,%3};"
        : "+f"(c[0]), "+f"(c[1]), "+f"(c[2]), "+f"(c[3])
        : "r"(a0), "r"(a1), "r"(a2), "r"(a3), "r"(b0), "r"(b1));
}

// ---------------------------------------------------------------------------
// tf32 rounding pass (fp32 -> tf32-rounded fp32)
// ---------------------------------------------------------------------------
__global__ void round_kernel(const float* __restrict__ src,
                             float* __restrict__ dst, int n4) {
    int i = blockIdx.x * 256 + threadIdx.x;
    if (i >= n4) return;
    float4 v = ((const float4*)src)[i];
    v.x = tf32r(v.x); v.y = tf32r(v.y); v.z = tf32r(v.z); v.w = tf32r(v.w);
    ((float4*)dst)[i] = v;
}

// ---------------------------------------------------------------------------
// Bias gather
// ---------------------------------------------------------------------------
__global__ void bias_kernel(const float* __restrict__ rpb,
                            const int* __restrict__ rpi) {
    int i = blockIdx.x * 256 + threadIdx.x;
    if (i >= NH * NT * NT) return;
    int h  = i / (NT * NT);
    int qk = i - h * (NT * NT);
    g_bias[i] = rpb[rpi[qk] * NH + h];
}

// ---------------------------------------------------------------------------
// Single-pass TF32 GEMM (R8/R11 version — proven best, unchanged)
// ---------------------------------------------------------------------------
#define STG 32768                // A 16KB + W 16KB per stage
#define SMT (3 * STG)            // 96 KB (3 stages)

template <int EPI>
__global__ void __launch_bounds__(256, 2)
tf_gemm(const float* __restrict__ A, const float* __restrict__ W,
        const float* __restrict__ bias, float* __restrict__ out) {
    extern __shared__ char smem[];
    const uint32_t sb = smem_u32(smem);

    const int tid  = threadIdx.x;
    const int warp = tid >> 5;
    const int lane = tid & 31;
    const int m0 = blockIdx.y * 128;
    const int n0 = blockIdx.x * 128;

    const int wm = (warp >> 2) * 64;    // 0 or 64
    const int wn = (warp & 3) * 32;     // 0,32,64,96

    const int lrow = tid >> 1;
    const int lcb  = (tid & 1) * 4;
    const float* Ap = A + (size_t)(m0 + lrow) * KDIM + lcb * 4;
    const float* Wp = W + (size_t)(n0 + lrow) * KDIM + lcb * 4;
    const uint32_t lbase = lrow * 128;
    const int lsw = lrow & 7;

    auto fill = [&](int kc, int s) {
        const uint32_t base = sb + s * STG;
#pragma unroll
        for (int c = 0; c < 4; c++) {
            const uint32_t off = lbase + (((uint32_t)((lcb + c) ^ lsw)) << 4);
            CP_ASYNC16(base + off,         Ap + kc * 32 + c * 4);
            CP_ASYNC16(base + 16384 + off, Wp + kc * 32 + c * 4);
        }
    };

    float acc[4][4][4];
#pragma unroll
    for (int i = 0; i < 4; i++)
#pragma unroll
        for (int j = 0; j < 4; j++)
#pragma unroll
            for (int r = 0; r < 4; r++) acc[i][j][r] = 0.0f;

    const int mat = lane >> 3;      // 0..3
    const int mr  = lane & 7;       // 0..7

    fill(0, 0); CP_COMMIT();
    fill(1, 1); CP_COMMIT();

    int scur = 0;
    int snxt = 2;
    for (int kc = 0; kc < 12; ++kc) {
        if (kc + 2 < 12) { CP_WAIT(1); } else { CP_WAIT(0); }
        __syncthreads();
        if (kc + 2 < 12) {
            fill(kc + 2, snxt);
            CP_COMMIT();
        }

        const uint32_t smA = sb + scur * STG;
        const uint32_t smW = smA + 16384;
        scur = (scur + 1 == 3) ? 0 : scur + 1;
        snxt = (snxt + 1 == 3) ? 0 : snxt + 1;

#pragma unroll
        for (int kg = 0; kg < 4; kg++) {
            uint32_t af[4][4];
            const uint32_t achunk = ((uint32_t)(kg * 2 + (mat >> 1)) ^ (uint32_t)mr) << 4;
            const uint32_t arow   = wm + ((mat & 1) << 3) + mr;
#pragma unroll
            for (int tm = 0; tm < 4; tm++) {
                const uint32_t ad = smA + (arow + tm * 16) * 128 + achunk;
                ldsm4(af[tm][0], af[tm][1], af[tm][2], af[tm][3], ad);
            }
            uint32_t bf[4][2];
            const uint32_t bchunk = ((uint32_t)(kg * 2 + (mat & 1)) ^ (uint32_t)mr) << 4;
#pragma unroll
            for (int p = 0; p < 2; p++) {
                const uint32_t brow = wn + (2 * p + (mat >> 1)) * 8 + mr;
                const uint32_t bd = smW + brow * 128 + bchunk;
                uint32_t t0, t1, t2, t3;
                ldsm4(t0, t1, t2, t3, bd);
                bf[2 * p][0] = t0; bf[2 * p][1] = t1;
                bf[2 * p + 1][0] = t2; bf[2 * p + 1][1] = t3;
            }
#pragma unroll
            for (int tm = 0; tm < 4; tm++)
#pragma unroll
                for (int tn = 0; tn < 4; tn++)
                    mma_tf32(acc[tm][tn], af[tm][0], af[tm][1], af[tm][2], af[tm][3],
                             bf[tn][0], bf[tn][1]);
        }
    }

    const int rA = lane >> 2;
    const int cA = lane & 3;
#pragma unroll
    for (int tm = 0; tm < 4; tm++) {
#pragma unroll
        for (int tn = 0; tn < 4; tn++) {
#pragma unroll
            for (int half = 0; half < 2; half++) {
                const int m = m0 + wm + tm * 16 + rA + half * 8;
                const int n = n0 + wn + tn * 8 + cA * 2;
                float v0 = acc[tm][tn][half * 2 + 0] + bias[n];
                float v1 = acc[tm][tn][half * 2 + 1] + bias[n + 1];
                if (EPI == 0) {
                    const int s   = n / NC;
                    const int rem = n - s * NC;
                    const int h   = rem >> 5;
                    const int d0  = rem & 31;
                    if (s == 0) {
                        const float sc = 0.17677669529663687f;  // 1/sqrt(32)
                        v0 *= sc; v1 *= sc;
                    }
                    const int b = m >> 6;
                    const int t = m & 63;
                    float* dst = g_qkv + (size_t)s * SQ +
                                 (((size_t)(b * NH + h)) * NT + t) * ND + d0;
                    // tf32-round here so attention needs ZERO cvt
                    *(float2*)dst = make_float2(tf32r(v0), tf32r(v1));
                } else {
                    *(float2*)(out + (size_t)m * NC + n) = make_float2(v0, v1);
                }
            }
        }
    }
}

// ---------------------------------------------------------------------------
// Attention: one CTA per (b,h). Single-pass tf32.
// NEW: cp.async staging in two groups ({K,Q} then {V}) so V's DRAM latency
// hides behind QK^T + softmax; bias prefetched to registers before the mma.
// ---------------------------------------------------------------------------
__global__ void __launch_bounds__(256) attn_kernel() {
    __shared__ __align__(16) float Qs[64][36];
    __shared__ __align__(16) float Ks[64][36];
    __shared__ __align__(16) float Vs[64][36];
    __shared__ float Ss[64][68];

    const int bh  = blockIdx.x;
    const int h   = bh % NH;
    const int tid = threadIdx.x;

    const float* Qg = g_qkv + (size_t)bh * NT * ND;
    const float* Kg = g_qkv + SQ + (size_t)bh * NT * ND;
    const float* Vg = g_qkv + 2 * SQ + (size_t)bh * NT * ND;

    const uint32_t sQ = smem_u32(&Qs[0][0]);
    const uint32_t sK = smem_u32(&Ks[0][0]);
    const uint32_t sV = smem_u32(&Vs[0][0]);

    // 512 16B-chunks per tensor; 2 per thread. Row pitch 144B (16B aligned).
    {
        const int c0 = tid * 2;
#pragma unroll
        for (int j = 0; j < 2; j++) {
            const int c = c0 + j;
            const int row = c >> 3;
            const int cb  = c & 7;
            const uint32_t soff = row * 144 + cb * 16;
            const size_t goff = (size_t)row * 32 + cb * 4;
            CP_ASYNC16(sK + soff, Kg + goff);
            CP_ASYNC16(sQ + soff, Qg + goff);
        }
        CP_COMMIT();                      // group 1: K + Q
#pragma unroll
        for (int j = 0; j < 2; j++) {
            const int c = c0 + j;
            const int row = c >> 3;
            const int cb  = c & 7;
            CP_ASYNC16(sV + row * 144 + cb * 16, Vg + (size_t)row * 32 + cb * 4);
        }
        CP_COMMIT();                      // group 2: V
    }

    const int lane = tid & 31;
    const int warp = tid >> 5;
    const int rA = lane >> 2;
    const int cA = lane & 3;
    const int wm = (warp >> 1) * 16;
    const int wn = (warp & 1) * 32;

    // prefetch bias to registers (L2 loads overlap the QK^T mma below)
    const float* bp = g_bias + h * NT * NT;
    float2 bzv[4][2];
#pragma unroll
    for (int tn = 0; tn < 4; tn++)
#pragma unroll
        for (int half = 0; half < 2; half++) {
            const int m = wm + rA + half * 8;
            const int n = wn + tn * 8 + cA * 2;
            bzv[tn][half] = *(const float2*)(bp + m * NT + n);
        }

    CP_WAIT(1);            // K, Q resident (V may still be in flight)
    __syncthreads();

    // S = Q K^T (single-pass tf32; operands already tf32-valued)
    float sc_[4][4];
#pragma unroll
    for (int i = 0; i < 4; i++)
#pragma unroll
        for (int r = 0; r < 4; r++) sc_[i][r] = 0.0f;

#pragma unroll
    for (int k0 = 0; k0 < 32; k0 += 8) {
        uint32_t a0 = __float_as_uint(Qs[wm + rA][k0 + cA]);
        uint32_t a1 = __float_as_uint(Qs[wm + 8 + rA][k0 + cA]);
        uint32_t a2 = __float_as_uint(Qs[wm + rA][k0 + 4 + cA]);
        uint32_t a3 = __float_as_uint(Qs[wm + 8 + rA][k0 + 4 + cA]);
#pragma unroll
        for (int tn = 0; tn < 4; tn++) {
            const int kr = wn + tn * 8 + rA;
            uint32_t b0 = __float_as_uint(Ks[kr][k0 + cA]);
            uint32_t b1 = __float_as_uint(Ks[kr][k0 + 4 + cA]);
            mma_tf32(sc_[tn], a0, a1, a2, a3, b0, b1);
        }
    }

#pragma unroll
    for (int tn = 0; tn < 4; tn++) {
#pragma unroll
        for (int half = 0; half < 2; half++) {
            const int m = wm + rA + half * 8;
            const int n = wn + tn * 8 + cA * 2;
            *(float2*)&Ss[m][n] = make_float2(sc_[tn][half * 2 + 0] + bzv[tn][half].x,
                                              sc_[tn][half * 2 + 1] + bzv[tn][half].y);
        }
    }
    __syncthreads();

    // softmax: 8 warps x 8 rows; emit tf32-rounded probabilities
#pragma unroll
    for (int r = warp * 8; r < warp * 8 + 8; ++r) {
        float v0 = Ss[r][lane];
        float v1 = Ss[r][lane + 32];
        float mx = fmaxf(v0, v1);
#pragma unroll
        for (int o = 16; o; o >>= 1)
            mx = fmaxf(mx, __shfl_xor_sync(0xffffffffu, mx, o));
        float e0 = __expf(v0 - mx);
        float e1 = __expf(v1 - mx);
        float sm = e0 + e1;
#pragma unroll
        for (int o = 16; o; o >>= 1)
            sm += __shfl_xor_sync(0xffffffffu, sm, o);
        float inv = 1.0f / sm;
        Ss[r][lane]      = tf32r(e0 * inv);
        Ss[r][lane + 32] = tf32r(e1 * inv);
    }
    CP_WAIT(0);            // V resident
    __syncthreads();

    // O = P V (single-pass tf32)
    const int wn2 = (warp & 1) * 16;
    float oc[2][4];
#pragma unroll
    for (int i = 0; i < 2; i++)
#pragma unroll
        for (int r = 0; r < 4; r++) oc[i][r] = 0.0f;

#pragma unroll
    for (int k0 = 0; k0 < 64; k0 += 8) {
        uint32_t a0 = __float_as_uint(Ss[wm + rA][k0 + cA]);
        uint32_t a1 = __float_as_uint(Ss[wm + 8 + rA][k0 + cA]);
        uint32_t a2 = __float_as_uint(Ss[wm + rA][k0 + 4 + cA]);
        uint32_t a3 = __float_as_uint(Ss[wm + 8 + rA][k0 + 4 + cA]);
#pragma unroll
        for (int tn = 0; tn < 2; tn++) {
            const int dc = wn2 + tn * 8 + rA;
            uint32_t b0 = __float_as_uint(Vs[k0 + cA][dc]);
            uint32_t b1 = __float_as_uint(Vs[k0 + 4 + cA][dc]);
            mma_tf32(oc[tn], a0, a1, a2, a3, b0, b1);
        }
    }

    const int b = bh / NH;
#pragma unroll
    for (int tn = 0; tn < 2; tn++) {
#pragma unroll
        for (int half = 0; half < 2; half++) {
            const int t = wm + rA + half * 8;
            const int d = wn2 + tn * 8 + cA * 2;
            // tf32-round so the proj GEMM can run single-pass
            float2 w2 = make_float2(tf32r(oc[tn][half * 2 + 0]),
                                    tf32r(oc[tn][half * 2 + 1]));
            *(float2*)&g_att[((size_t)(b * NT + t)) * NC + h * ND + d] = w2;
        }
    }
}

// ---------------------------------------------------------------------------
// Launch  (order arranged so launch #4 = tf_gemm<0> for ncu capture)
// ---------------------------------------------------------------------------
extern "C" void kernel_launch(void* const* d_in, const int* in_sizes, int n_in,
                              void* d_out, int out_size) {
    const float* x      = (const float*)d_in[0];
    const float* qkv_w  = (const float*)d_in[1];
    const float* qkv_b  = (const float*)d_in[2];
    const float* proj_w = (const float*)d_in[3];
    const float* proj_b = (const float*)d_in[4];
    const float* rpb    = (const float*)d_in[5];
    const int*   rpi    = (const int*)d_in[6];
    float* out = (float*)d_out;

    cudaFuncSetAttribute(tf_gemm<0>, cudaFuncAttributeMaxDynamicSharedMemorySize, SMT);
    cudaFuncSetAttribute(tf_gemm<1>, cudaFuncAttributeMaxDynamicSharedMemorySize, SMT);

    float *xt, *qwt, *pwt, *att;
    cudaGetSymbolAddress((void**)&xt,  g_xt);
    cudaGetSymbolAddress((void**)&qwt, g_qwt);
    cudaGetSymbolAddress((void**)&pwt, g_pwt);
    cudaGetSymbolAddress((void**)&att, g_att);

    // tf32 pre-rounding (launches 1-3)
    {
        int n4 = (MT * NC) / 4;
        round_kernel<<<(n4 + 255) / 256, 256>>>(x, xt, n4);
        n4 = (N3C * NC) / 4;
        round_kernel<<<(n4 + 255) / 256, 256>>>(qkv_w, qwt, n4);
        n4 = (NC * NC) / 4;
        round_kernel<<<(n4 + 255) / 256, 256>>>(proj_w, pwt, n4);
    }

    // launch 4: the big QKV GEMM (profiled slot)
    dim3 g1(N3C / 128, MT / 128);   // (9, 1024)
    tf_gemm<0><<<g1, 256, SMT>>>(xt, qwt, qkv_b, nullptr);

    // launch 5: bias gather (only needed before attn)
    bias_kernel<<<(NH * NT * NT + 255) / 256, 256>>>(rpb, rpi);

    // launch 6: attention
    attn_kernel<<<NB * NH, 256>>>();

    // launch 7: projection GEMM
    dim3 g2(NC / 128, MT / 128);    // (3, 1024)
    tf_gemm<1><<<g2, 256, SMT>>>(att, pwt, proj_b, out);
}

// round 13
// speedup vs baseline: 1.1457x; 1.0154x over previous
#include <cuda_runtime.h>
#include <cstdint>

// Problem constants
#define NB 2048
#define NT 64
#define NC 384
#define NH 12
#define ND 32
#define N3C 1152
#define MT 131072            // NB*NT rows
#define KDIM 384
#define SQ 50331648ull       // NB*NH*NT*ND

// ---------------- device scratch (no allocation allowed) -------------------
__device__ float g_qkv[3 * SQ];                     // (3,B,H,T,D) tf32-valued fp32
__device__ float g_bias[NH * NT * NT];              // (H,T,T)
__device__ float g_xt[(size_t)MT * NC];             // tf32-rounded x
__device__ float g_qwt[(size_t)N3C * NC];           // tf32-rounded qkv_w
__device__ float g_pwt[(size_t)NC * NC];            // tf32-rounded proj_w
__device__ float g_att[(size_t)MT * NC];            // attn output (tf32-rounded)

// ---------------- helpers ---------------------------------------------------
__device__ __forceinline__ uint32_t smem_u32(const void* p) {
    uint32_t a;
    asm("{ .reg .u64 t; cvta.to.shared.u64 t, %1; cvt.u32.u64 %0, t; }"
        : "=r"(a) : "l"(p));
    return a;
}
__device__ __forceinline__ float tf32r(float x) {
    uint32_t u; asm("cvt.rna.tf32.f32 %0, %1;" : "=r"(u) : "f"(x));
    return __uint_as_float(u);
}

#define CP_ASYNC16(dst, src) \
    asm volatile("cp.async.cg.shared.global [%0], [%1], 16;" \
                 :: "r"(dst), "l"(src) : "memory")
#define CP_COMMIT() asm volatile("cp.async.commit_group;" ::: "memory")
#define CP_WAIT(n)  asm volatile("cp.async.wait_group %0;" :: "n"(n) : "memory")

__device__ __forceinline__ void ldsm4(uint32_t& r0, uint32_t& r1,
                                      uint32_t& r2, uint32_t& r3, uint32_t a) {
    asm volatile("ldmatrix.sync.aligned.m8n8.x4.shared.b16 {%0,%1,%2,%3}, [%4];"
                 : "=r"(r0), "=r"(r1), "=r"(r2), "=r"(r3) : "r"(a));
}

__device__ __forceinline__ void mma_tf32(float c[4],
                                         uint32_t a0, uint32_t a1, uint32_t a2, uint32_t a3,
                                         uint32_t b0, uint32_t b1) {
    asm volatile(
        "mma.sync.aligned.m16n8k8.row.col.f32.tf32.tf32.f32 "
        "{%0,%1,%2,%3},{%4,%5,%6,%7},{%8,%9},{%0,%1,%2,%3};"
        : "+f"(c[0]), "+f"(c[1]), "+f"(c[2]), "+f"(c[3])
        : "r"(a0), "r"(a1), "r"(a2), "r"(a3), "r"(b0), "r"(b1));
}

// ---------------------------------------------------------------------------
// tf32 rounding pass (fp32 -> tf32-rounded fp32)
// ---------------------------------------------------------------------------
__global__ void round_kernel(const float* __restrict__ src,
                             float* __restrict__ dst, int n4) {
    int i = blockIdx.x * 256 + threadIdx.x;
    if (i >= n4) return;
    float4 v = ((const float4*)src)[i];
    v.x = tf32r(v.x); v.y = tf32r(v.y); v.z = tf32r(v.z); v.w = tf32r(v.w);
    ((float4*)dst)[i] = v;
}

// ---------------------------------------------------------------------------
// Bias gather
// ---------------------------------------------------------------------------
__global__ void bias_kernel(const float* __restrict__ rpb,
                            const int* __restrict__ rpi) {
    int i = blockIdx.x * 256 + threadIdx.x;
    if (i >= NH * NT * NT) return;
    int h  = i / (NT * NT);
    int qk = i - h * (NT * NT);
    g_bias[i] = rpb[rpi[qk] * NH + h];
}

// ---------------------------------------------------------------------------
// Single-pass TF32 GEMM (R8/R11 version — proven best, unchanged)
// ---------------------------------------------------------------------------
#define STG 32768                // A 16KB + W 16KB per stage
#define SMT (3 * STG)            // 96 KB (3 stages)

template <int EPI>
__global__ void __launch_bounds__(256, 2)
tf_gemm(const float* __restrict__ A, const float* __restrict__ W,
        const float* __restrict__ bias, float* __restrict__ out) {
    extern __shared__ char smem[];
    const uint32_t sb = smem_u32(smem);

    const int tid  = threadIdx.x;
    const int warp = tid >> 5;
    const int lane = tid & 31;
    const int m0 = blockIdx.y * 128;
    const int n0 = blockIdx.x * 128;

    const int wm = (warp >> 2) * 64;    // 0 or 64
    const int wn = (warp & 3) * 32;     // 0,32,64,96

    const int lrow = tid >> 1;
    const int lcb  = (tid & 1) * 4;
    const float* Ap = A + (size_t)(m0 + lrow) * KDIM + lcb * 4;
    const float* Wp = W + (size_t)(n0 + lrow) * KDIM + lcb * 4;
    const uint32_t lbase = lrow * 128;
    const int lsw = lrow & 7;

    auto fill = [&](int kc, int s) {
        const uint32_t base = sb + s * STG;
#pragma unroll
        for (int c = 0; c < 4; c++) {
            const uint32_t off = lbase + (((uint32_t)((lcb + c) ^ lsw)) << 4);
            CP_ASYNC16(base + off,         Ap + kc * 32 + c * 4);
            CP_ASYNC16(base + 16384 + off, Wp + kc * 32 + c * 4);
        }
    };

    float acc[4][4][4];
#pragma unroll
    for (int i = 0; i < 4; i++)
#pragma unroll
        for (int j = 0; j < 4; j++)
#pragma unroll
            for (int r = 0; r < 4; r++) acc[i][j][r] = 0.0f;

    const int mat = lane >> 3;      // 0..3
    const int mr  = lane & 7;       // 0..7

    fill(0, 0); CP_COMMIT();
    fill(1, 1); CP_COMMIT();

    int scur = 0;
    int snxt = 2;
    for (int kc = 0; kc < 12; ++kc) {
        if (kc + 2 < 12) { CP_WAIT(1); } else { CP_WAIT(0); }
        __syncthreads();
        if (kc + 2 < 12) {
            fill(kc + 2, snxt);
            CP_COMMIT();
        }

        const uint32_t smA = sb + scur * STG;
        const uint32_t smW = smA + 16384;
        scur = (scur + 1 == 3) ? 0 : scur + 1;
        snxt = (snxt + 1 == 3) ? 0 : snxt + 1;

#pragma unroll
        for (int kg = 0; kg < 4; kg++) {
            uint32_t af[4][4];
            const uint32_t achunk = ((uint32_t)(kg * 2 + (mat >> 1)) ^ (uint32_t)mr) << 4;
            const uint32_t arow   = wm + ((mat & 1) << 3) + mr;
#pragma unroll
            for (int tm = 0; tm < 4; tm++) {
                const uint32_t ad = smA + (arow + tm * 16) * 128 + achunk;
                ldsm4(af[tm][0], af[tm][1], af[tm][2], af[tm][3], ad);
            }
            uint32_t bf[4][2];
            const uint32_t bchunk = ((uint32_t)(kg * 2 + (mat & 1)) ^ (uint32_t)mr) << 4;
#pragma unroll
            for (int p = 0; p < 2; p++) {
                const uint32_t brow = wn + (2 * p + (mat >> 1)) * 8 + mr;
                const uint32_t bd = smW + brow * 128 + bchunk;
                uint32_t t0, t1, t2, t3;
                ldsm4(t0, t1, t2, t3, bd);
                bf[2 * p][0] = t0; bf[2 * p][1] = t1;
                bf[2 * p + 1][0] = t2; bf[2 * p + 1][1] = t3;
            }
#pragma unroll
            for (int tm = 0; tm < 4; tm++)
#pragma unroll
                for (int tn = 0; tn < 4; tn++)
                    mma_tf32(acc[tm][tn], af[tm][0], af[tm][1], af[tm][2], af[tm][3],
                             bf[tn][0], bf[tn][1]);
        }
    }

    const int rA = lane >> 2;
    const int cA = lane & 3;
#pragma unroll
    for (int tm = 0; tm < 4; tm++) {
#pragma unroll
        for (int tn = 0; tn < 4; tn++) {
#pragma unroll
            for (int half = 0; half < 2; half++) {
                const int m = m0 + wm + tm * 16 + rA + half * 8;
                const int n = n0 + wn + tn * 8 + cA * 2;
                float v0 = acc[tm][tn][half * 2 + 0] + bias[n];
                float v1 = acc[tm][tn][half * 2 + 1] + bias[n + 1];
                if (EPI == 0) {
                    const int s   = n / NC;
                    const int rem = n - s * NC;
                    const int h   = rem >> 5;
                    const int d0  = rem & 31;
                    if (s == 0) {
                        const float sc = 0.17677669529663687f;  // 1/sqrt(32)
                        v0 *= sc; v1 *= sc;
                    }
                    const int b = m >> 6;
                    const int t = m & 63;
                    float* dst = g_qkv + (size_t)s * SQ +
                                 (((size_t)(b * NH + h)) * NT + t) * ND + d0;
                    // tf32-round here so attention needs ZERO cvt
                    *(float2*)dst = make_float2(tf32r(v0), tf32r(v1));
                } else {
                    *(float2*)(out + (size_t)m * NC + n) = make_float2(v0, v1);
                }
            }
        }
    }
}

// ---------------------------------------------------------------------------
// Attention: one CTA per (b,h). Single-pass tf32.
// R13: Q/K/P fragment loads via ldmatrix (odd pitch = natural swizzle),
//      softmax without max-subtraction (scores bounded ~|7|, exp safe).
// ---------------------------------------------------------------------------
__global__ void __launch_bounds__(256) attn_kernel() {
    __shared__ __align__(16) float Qs[64][36];   // pitch 144B = 9x16B (conflict-free ldsm)
    __shared__ __align__(16) float Ks[64][36];
    __shared__ __align__(16) float Vs[64][36];
    __shared__ __align__(16) float Ss[64][68];   // pitch 272B = 17x16B

    const int bh  = blockIdx.x;
    const int h   = bh % NH;
    const int tid = threadIdx.x;

    const float* Qg = g_qkv + (size_t)bh * NT * ND;
    const float* Kg = g_qkv + SQ + (size_t)bh * NT * ND;
    const float* Vg = g_qkv + 2 * SQ + (size_t)bh * NT * ND;

    const uint32_t sQ = smem_u32(&Qs[0][0]);
    const uint32_t sK = smem_u32(&Ks[0][0]);
    const uint32_t sV = smem_u32(&Vs[0][0]);
    const uint32_t sS = smem_u32(&Ss[0][0]);

    // 512 16B-chunks per tensor; 2 per thread. Row pitch 144B.
    {
        const int c0 = tid * 2;
#pragma unroll
        for (int j = 0; j < 2; j++) {
            const int c = c0 + j;
            const int row = c >> 3;
            const int cb  = c & 7;
            const uint32_t soff = row * 144 + cb * 16;
            const size_t goff = (size_t)row * 32 + cb * 4;
            CP_ASYNC16(sK + soff, Kg + goff);
            CP_ASYNC16(sQ + soff, Qg + goff);
        }
        CP_COMMIT();                      // group 1: K + Q
#pragma unroll
        for (int j = 0; j < 2; j++) {
            const int c = c0 + j;
            const int row = c >> 3;
            const int cb  = c & 7;
            CP_ASYNC16(sV + row * 144 + cb * 16, Vg + (size_t)row * 32 + cb * 4);
        }
        CP_COMMIT();                      // group 2: V
    }

    const int lane = tid & 31;
    const int warp = tid >> 5;
    const int rA = lane >> 2;
    const int cA = lane & 3;
    const int wm = (warp >> 1) * 16;
    const int wn = (warp & 1) * 32;
    const int mat = lane >> 3;
    const int mr  = lane & 7;

    // fragment base addresses (ldmatrix row addressing)
    const uint32_t qrow  = sQ + (uint32_t)(wm + ((mat & 1) << 3) + mr) * 144;
    const uint32_t srow  = sS + (uint32_t)(wm + ((mat & 1) << 3) + mr) * 272;
    const uint32_t krow0 = sK + (uint32_t)(wn + ((mat >> 1) * 8) + mr) * 144;
    const uint32_t krow1 = sK + (uint32_t)(wn + ((2 + (mat >> 1)) * 8) + mr) * 144;
    const uint32_t akoff = ((uint32_t)(mat >> 1)) << 4;   // +0 or +16 bytes (k-half for A)
    const uint32_t bkoff = ((uint32_t)(mat & 1)) << 4;    // k-half for B

    // prefetch bias to registers (L2 loads overlap the QK^T mma below)
    const float* bp = g_bias + h * NT * NT;
    float2 bzv[4][2];
#pragma unroll
    for (int tn = 0; tn < 4; tn++)
#pragma unroll
        for (int half = 0; half < 2; half++) {
            const int m = wm + rA + half * 8;
            const int n = wn + tn * 8 + cA * 2;
            bzv[tn][half] = *(const float2*)(bp + m * NT + n);
        }

    CP_WAIT(1);            // K, Q resident (V may still be in flight)
    __syncthreads();

    // S = Q K^T (single-pass tf32, ldmatrix fragments)
    float sc_[4][4];
#pragma unroll
    for (int i = 0; i < 4; i++)
#pragma unroll
        for (int r = 0; r < 4; r++) sc_[i][r] = 0.0f;

#pragma unroll
    for (int k0 = 0; k0 < 32; k0 += 8) {
        uint32_t a0, a1, a2, a3;
        ldsm4(a0, a1, a2, a3, qrow + k0 * 4 + akoff);
        uint32_t t0, t1, t2, t3;
        ldsm4(t0, t1, t2, t3, krow0 + k0 * 4 + bkoff);
        mma_tf32(sc_[0], a0, a1, a2, a3, t0, t1);
        mma_tf32(sc_[1], a0, a1, a2, a3, t2, t3);
        ldsm4(t0, t1, t2, t3, krow1 + k0 * 4 + bkoff);
        mma_tf32(sc_[2], a0, a1, a2, a3, t0, t1);
        mma_tf32(sc_[3], a0, a1, a2, a3, t2, t3);
    }

#pragma unroll
    for (int tn = 0; tn < 4; tn++) {
#pragma unroll
        for (int half = 0; half < 2; half++) {
            const int m = wm + rA + half * 8;
            const int n = wn + tn * 8 + cA * 2;
            *(float2*)&Ss[m][n] = make_float2(sc_[tn][half * 2 + 0] + bzv[tn][half].x,
                                              sc_[tn][half * 2 + 1] + bzv[tn][half].y);
        }
    }
    __syncthreads();

    // softmax without max-subtraction (scores bounded; exp safe in fp32)
#pragma unroll
    for (int r = warp * 8; r < warp * 8 + 8; ++r) {
        float e0 = __expf(Ss[r][lane]);
        float e1 = __expf(Ss[r][lane + 32]);
        float sm = e0 + e1;
#pragma unroll
        for (int o = 16; o; o >>= 1)
            sm += __shfl_xor_sync(0xffffffffu, sm, o);
        float inv = 1.0f / sm;
        Ss[r][lane]      = tf32r(e0 * inv);
        Ss[r][lane + 32] = tf32r(e1 * inv);
    }
    CP_WAIT(0);            // V resident
    __syncthreads();

    // O = P V (single-pass tf32; P fragments via ldmatrix, V scalar)
    const int wn2 = (warp & 1) * 16;
    float oc[2][4];
#pragma unroll
    for (int i = 0; i < 2; i++)
#pragma unroll
        for (int r = 0; r < 4; r++) oc[i][r] = 0.0f;

#pragma unroll
    for (int k0 = 0; k0 < 64; k0 += 8) {
        uint32_t a0, a1, a2, a3;
        ldsm4(a0, a1, a2, a3, srow + k0 * 4 + akoff);
#pragma unroll
        for (int tn = 0; tn < 2; tn++) {
            const int dc = wn2 + tn * 8 + rA;
            uint32_t b0 = __float_as_uint(Vs[k0 + cA][dc]);
            uint32_t b1 = __float_as_uint(Vs[k0 + 4 + cA][dc]);
            mma_tf32(oc[tn], a0, a1, a2, a3, b0, b1);
        }
    }

    const int b = bh / NH;
#pragma unroll
    for (int tn = 0; tn < 2; tn++) {
#pragma unroll
        for (int half = 0; half < 2; half++) {
            const int t = wm + rA + half * 8;
            const int d = wn2 + tn * 8 + cA * 2;
            // tf32-round so the proj GEMM can run single-pass
            float2 w2 = make_float2(tf32r(oc[tn][half * 2 + 0]),
                                    tf32r(oc[tn][half * 2 + 1]));
            *(float2*)&g_att[((size_t)(b * NT + t)) * NC + h * ND + d] = w2;
        }
    }
}

// ---------------------------------------------------------------------------
// Launch  (order arranged so launch #4 = tf_gemm<0> for ncu capture)
// ---------------------------------------------------------------------------
extern "C" void kernel_launch(void* const* d_in, const int* in_sizes, int n_in,
                              void* d_out, int out_size) {
    const float* x      = (const float*)d_in[0];
    const float* qkv_w  = (const float*)d_in[1];
    const float* qkv_b  = (const float*)d_in[2];
    const float* proj_w = (const float*)d_in[3];
    const float* proj_b = (const float*)d_in[4];
    const float* rpb    = (const float*)d_in[5];
    const int*   rpi    = (const int*)d_in[6];
    float* out = (float*)d_out;

    cudaFuncSetAttribute(tf_gemm<0>, cudaFuncAttributeMaxDynamicSharedMemorySize, SMT);
    cudaFuncSetAttribute(tf_gemm<1>, cudaFuncAttributeMaxDynamicSharedMemorySize, SMT);

    float *xt, *qwt, *pwt, *att;
    cudaGetSymbolAddress((void**)&xt,  g_xt);
    cudaGetSymbolAddress((void**)&qwt, g_qwt);
    cudaGetSymbolAddress((void**)&pwt, g_pwt);
    cudaGetSymbolAddress((void**)&att, g_att);

    // tf32 pre-rounding (launches 1-3)
    {
        int n4 = (MT * NC) / 4;
        round_kernel<<<(n4 + 255) / 256, 256>>>(x, xt, n4);
        n4 = (N3C * NC) / 4;
        round_kernel<<<(n4 + 255) / 256, 256>>>(qkv_w, qwt, n4);
        n4 = (NC * NC) / 4;
        round_kernel<<<(n4 + 255) / 256, 256>>>(proj_w, pwt, n4);
    }

    // launch 4: the big QKV GEMM (profiled slot)
    dim3 g1(N3C / 128, MT / 128);   // (9, 1024)
    tf_gemm<0><<<g1, 256, SMT>>>(xt, qwt, qkv_b, nullptr);

    // launch 5: bias gather (only needed before attn)
    bias_kernel<<<(NH * NT * NT + 255) / 256, 256>>>(rpb, rpi);

    // launch 6: attention
    attn_kernel<<<NB * NH, 256>>>();

    // launch 7: projection GEMM
    dim3 g2(NC / 128, MT / 128);    // (3, 1024)
    tf_gemm<1><<<g2, 256, SMT>>>(att, pwt, proj_b, out);
}

// round 14
// speedup vs baseline: 1.6942x; 1.4787x over previous
#include <cuda_runtime.h>
#include <cuda_fp16.h>
#include <cstdint>

// Problem constants
#define NB 2048
#define NT 64
#define NC 384
#define NH 12
#define ND 32
#define N3C 1152
#define MT 131072            // NB*NT rows
#define KDIM 384
#define SQ 50331648ull       // NB*NH*NT*ND

// ---------------- device scratch (no allocation allowed) -------------------
__device__ float g_qkv[3 * SQ];                     // (3,B,H,T,D) tf32-valued fp32
__device__ float g_bias[NH * NT * NT];              // (H,T,T)
__device__ __half g_xh[(size_t)MT * NC];            // fp16 x
__device__ __half g_qwh[(size_t)N3C * NC];          // fp16 qkv_w
__device__ __half g_pwh[(size_t)NC * NC];           // fp16 proj_w
__device__ __half g_atth[(size_t)MT * NC];          // attn output (fp16)

// ---------------- helpers ---------------------------------------------------
__device__ __forceinline__ uint32_t smem_u32(const void* p) {
    uint32_t a;
    asm("{ .reg .u64 t; cvta.to.shared.u64 t, %1; cvt.u32.u64 %0, t; }"
        : "=r"(a) : "l"(p));
    return a;
}
__device__ __forceinline__ float tf32r(float x) {
    uint32_t u; asm("cvt.rna.tf32.f32 %0, %1;" : "=r"(u) : "f"(x));
    return __uint_as_float(u);
}

#define CP_ASYNC16(dst, src) \
    asm volatile("cp.async.cg.shared.global [%0], [%1], 16;" \
                 :: "r"(dst), "l"(src) : "memory")
#define CP_COMMIT() asm volatile("cp.async.commit_group;" ::: "memory")
#define CP_WAIT(n)  asm volatile("cp.async.wait_group %0;" :: "n"(n) : "memory")

__device__ __forceinline__ void ldsm4(uint32_t& r0, uint32_t& r1,
                                      uint32_t& r2, uint32_t& r3, uint32_t a) {
    asm volatile("ldmatrix.sync.aligned.m8n8.x4.shared.b16 {%0,%1,%2,%3}, [%4];"
                 : "=r"(r0), "=r"(r1), "=r"(r2), "=r"(r3) : "r"(a));
}

__device__ __forceinline__ void mma_f16(float c[4], const uint32_t a[4],
                                        const uint32_t b[2]) {
    asm volatile(
        "mma.sync.aligned.m16n8k16.row.col.f32.f16.f16.f32 "
        "{%0,%1,%2,%3},{%4,%5,%6,%7},{%8,%9},{%0,%1,%2,%3};"
        : "+f"(c[0]), "+f"(c[1]), "+f"(c[2]), "+f"(c[3])
        : "r"(a[0]), "r"(a[1]), "r"(a[2]), "r"(a[3]), "r"(b[0]), "r"(b[1]));
}

__device__ __forceinline__ void mma_tf32(float c[4],
                                         uint32_t a0, uint32_t a1, uint32_t a2, uint32_t a3,
                                         uint32_t b0, uint32_t b1) {
    asm volatile(
        "mma.sync.aligned.m16n8k8.row.col.f32.tf32.tf32.f32 "
        "{%0,%1,%2,%3},{%4,%5,%6,%7},{%8,%9},{%0,%1,%2,%3};"
        : "+f"(c[0]), "+f"(c[1]), "+f"(c[2]), "+f"(c[3])
        : "r"(a0), "r"(a1), "r"(a2), "r"(a3), "r"(b0), "r"(b1));
}

// ---------------------------------------------------------------------------
// fp32 -> fp16 conversion pass
// ---------------------------------------------------------------------------
__global__ void tohalf_kernel(const float* __restrict__ src,
                              __half* __restrict__ dst, int n4) {
    int i = blockIdx.x * 256 + threadIdx.x;
    if (i >= n4) return;
    float4 v = ((const float4*)src)[i];
    __half2 h01 = __floats2half2_rn(v.x, v.y);
    __half2 h23 = __floats2half2_rn(v.z, v.w);
    ((__half2*)dst)[2 * i]     = h01;
    ((__half2*)dst)[2 * i + 1] = h23;
}

// ---------------------------------------------------------------------------
// Bias gather
// ---------------------------------------------------------------------------
__global__ void bias_kernel(const float* __restrict__ rpb,
                            const int* __restrict__ rpi) {
    int i = blockIdx.x * 256 + threadIdx.x;
    if (i >= NH * NT * NT) return;
    int h  = i / (NT * NT);
    int qk = i - h * (NT * NT);
    g_bias[i] = rpb[rpi[qk] * NH + h];
}

// ---------------------------------------------------------------------------
// Single-pass FP16 HMMA GEMM: C[m][n] = sum_k A[m][k]*W[n][k] + bias[n]
// BM=BN=128, BK=64 halfs (128B SW-swizzled rows). 8 warps (2x4), warp 64x32.
// (fragment/swizzle math identical to the R4-verified bf16 kernel)
// 3-stage cp.async pipeline, one sync per iteration.
// EPI==0: scatter tf32-rounded fp32 into g_qkv with q-scale.
// EPI==1: write fp32 out (+bias).
// ---------------------------------------------------------------------------
#define HSTG 32768               // A 16KB + W 16KB per stage
#define SMH (3 * HSTG)           // 96 KB

template <int EPI>
__global__ void __launch_bounds__(256, 2)
h16_gemm(const __half* __restrict__ A, const __half* __restrict__ W,
         const float* __restrict__ bias, float* __restrict__ out) {
    extern __shared__ char smem[];
    const uint32_t sb = smem_u32(smem);

    const int tid  = threadIdx.x;
    const int warp = tid >> 5;
    const int lane = tid & 31;
    const int m0 = blockIdx.y * 128;
    const int n0 = blockIdx.x * 128;

    const int wm = (warp >> 2) * 64;    // 0 or 64
    const int wn = (warp & 3) * 32;     // 0,32,64,96

    // loaders: each thread cp.asyncs 4 chunks (16B) of A and of W per stage
    const int lrow = tid >> 1;
    const int lcb  = (tid & 1) * 4;
    const __half* Ap = A + (size_t)(m0 + lrow) * KDIM + lcb * 8;
    const __half* Wp = W + (size_t)(n0 + lrow) * KDIM + lcb * 8;
    const uint32_t lbase = lrow * 128;
    const int lsw = lrow & 7;

    auto fill = [&](int kc, int s) {
        const uint32_t base = sb + s * HSTG;
#pragma unroll
        for (int c = 0; c < 4; c++) {
            const uint32_t off = lbase + (((uint32_t)((lcb + c) ^ lsw)) << 4);
            CP_ASYNC16(base + off,         Ap + kc * 64 + c * 8);
            CP_ASYNC16(base + 16384 + off, Wp + kc * 64 + c * 8);
        }
    };

    float acc[4][4][4];
#pragma unroll
    for (int i = 0; i < 4; i++)
#pragma unroll
        for (int j = 0; j < 4; j++)
#pragma unroll
            for (int r = 0; r < 4; r++) acc[i][j][r] = 0.0f;

    const int mat = lane >> 3;      // 0..3
    const int mr  = lane & 7;       // 0..7

    fill(0, 0); CP_COMMIT();
    fill(1, 1); CP_COMMIT();

    int scur = 0;    // stage of kc
    int snxt = 2;    // stage of kc+2
    for (int kc = 0; kc < 6; ++kc) {
        if (kc + 2 < 6) { CP_WAIT(1); } else { CP_WAIT(0); }
        __syncthreads();
        if (kc + 2 < 6) {
            fill(kc + 2, snxt);
            CP_COMMIT();
        }

        const uint32_t smA = sb + scur * HSTG;
        const uint32_t smW = smA + 16384;
        scur = (scur + 1 == 3) ? 0 : scur + 1;
        snxt = (snxt + 1 == 3) ? 0 : snxt + 1;

#pragma unroll
        for (int kg = 0; kg < 4; kg++) {   // 4 x k16 per BK=64
            uint32_t af[4][4];
            const uint32_t achunk = ((uint32_t)(kg * 2 + (mat >> 1)) ^ (uint32_t)mr) << 4;
            const uint32_t arow   = wm + ((mat & 1) << 3) + mr;
#pragma unroll
            for (int tm = 0; tm < 4; tm++) {
                const uint32_t ad = smA + (arow + tm * 16) * 128 + achunk;
                ldsm4(af[tm][0], af[tm][1], af[tm][2], af[tm][3], ad);
            }
            uint32_t bf[4][2];
            const uint32_t bchunk = ((uint32_t)(kg * 2 + (mat & 1)) ^ (uint32_t)mr) << 4;
#pragma unroll
            for (int p = 0; p < 2; p++) {
                const uint32_t brow = wn + (2 * p + (mat >> 1)) * 8 + mr;
                const uint32_t bd = smW + brow * 128 + bchunk;
                uint32_t t0, t1, t2, t3;
                ldsm4(t0, t1, t2, t3, bd);
                bf[2 * p][0] = t0; bf[2 * p][1] = t1;
                bf[2 * p + 1][0] = t2; bf[2 * p + 1][1] = t3;
            }
#pragma unroll
            for (int tm = 0; tm < 4; tm++)
#pragma unroll
                for (int tn = 0; tn < 4; tn++)
                    mma_f16(acc[tm][tn], af[tm], bf[tn]);
        }
    }

    // epilogue: thread holds (rA, 2cA),(rA,2cA+1),(rA+8,..)
    const int rA = lane >> 2;
    const int cA = lane & 3;
#pragma unroll
    for (int tm = 0; tm < 4; tm++) {
#pragma unroll
        for (int tn = 0; tn < 4; tn++) {
#pragma unroll
            for (int half = 0; half < 2; half++) {
                const int m = m0 + wm + tm * 16 + rA + half * 8;
                const int n = n0 + wn + tn * 8 + cA * 2;
                float v0 = acc[tm][tn][half * 2 + 0] + bias[n];
                float v1 = acc[tm][tn][half * 2 + 1] + bias[n + 1];
                if (EPI == 0) {
                    const int s   = n / NC;
                    const int rem = n - s * NC;
                    const int h   = rem >> 5;
                    const int d0  = rem & 31;
                    if (s == 0) {
                        const float sc = 0.17677669529663687f;  // 1/sqrt(32)
                        v0 *= sc; v1 *= sc;
                    }
                    const int b = m >> 6;
                    const int t = m & 63;
                    float* dst = g_qkv + (size_t)s * SQ +
                                 (((size_t)(b * NH + h)) * NT + t) * ND + d0;
                    // tf32-round here so attention needs ZERO cvt
                    *(float2*)dst = make_float2(tf32r(v0), tf32r(v1));
                } else {
                    *(float2*)(out + (size_t)m * NC + n) = make_float2(v0, v1);
                }
            }
        }
    }
}

// ---------------------------------------------------------------------------
// Attention: one CTA per (b,h). Single-pass tf32 (R13 version, unchanged
// numerics) — output now written as fp16 for the fp16 proj GEMM.
// ---------------------------------------------------------------------------
__global__ void __launch_bounds__(256) attn_kernel() {
    __shared__ __align__(16) float Qs[64][36];   // pitch 144B (conflict-free ldsm)
    __shared__ __align__(16) float Ks[64][36];
    __shared__ __align__(16) float Vs[64][36];
    __shared__ __align__(16) float Ss[64][68];   // pitch 272B

    const int bh  = blockIdx.x;
    const int h   = bh % NH;
    const int tid = threadIdx.x;

    const float* Qg = g_qkv + (size_t)bh * NT * ND;
    const float* Kg = g_qkv + SQ + (size_t)bh * NT * ND;
    const float* Vg = g_qkv + 2 * SQ + (size_t)bh * NT * ND;

    const uint32_t sQ = smem_u32(&Qs[0][0]);
    const uint32_t sK = smem_u32(&Ks[0][0]);
    const uint32_t sV = smem_u32(&Vs[0][0]);
    const uint32_t sS = smem_u32(&Ss[0][0]);

    // 512 16B-chunks per tensor; 2 per thread. Row pitch 144B.
    {
        const int c0 = tid * 2;
#pragma unroll
        for (int j = 0; j < 2; j++) {
            const int c = c0 + j;
            const int row = c >> 3;
            const int cb  = c & 7;
            const uint32_t soff = row * 144 + cb * 16;
            const size_t goff = (size_t)row * 32 + cb * 4;
            CP_ASYNC16(sK + soff, Kg + goff);
            CP_ASYNC16(sQ + soff, Qg + goff);
        }
        CP_COMMIT();                      // group 1: K + Q
#pragma unroll
        for (int j = 0; j < 2; j++) {
            const int c = c0 + j;
            const int row = c >> 3;
            const int cb  = c & 7;
            CP_ASYNC16(sV + row * 144 + cb * 16, Vg + (size_t)row * 32 + cb * 4);
        }
        CP_COMMIT();                      // group 2: V
    }

    const int lane = tid & 31;
    const int warp = tid >> 5;
    const int rA = lane >> 2;
    const int cA = lane & 3;
    const int wm = (warp >> 1) * 16;
    const int wn = (warp & 1) * 32;
    const int mat = lane >> 3;
    const int mr  = lane & 7;

    const uint32_t qrow  = sQ + (uint32_t)(wm + ((mat & 1) << 3) + mr) * 144;
    const uint32_t srow  = sS + (uint32_t)(wm + ((mat & 1) << 3) + mr) * 272;
    const uint32_t krow0 = sK + (uint32_t)(wn + ((mat >> 1) * 8) + mr) * 144;
    const uint32_t krow1 = sK + (uint32_t)(wn + ((2 + (mat >> 1)) * 8) + mr) * 144;
    const uint32_t akoff = ((uint32_t)(mat >> 1)) << 4;
    const uint32_t bkoff = ((uint32_t)(mat & 1)) << 4;

    // prefetch bias to registers
    const float* bp = g_bias + h * NT * NT;
    float2 bzv[4][2];
#pragma unroll
    for (int tn = 0; tn < 4; tn++)
#pragma unroll
        for (int half = 0; half < 2; half++) {
            const int m = wm + rA + half * 8;
            const int n = wn + tn * 8 + cA * 2;
            bzv[tn][half] = *(const float2*)(bp + m * NT + n);
        }

    CP_WAIT(1);            // K, Q resident
    __syncthreads();

    // S = Q K^T
    float sc_[4][4];
#pragma unroll
    for (int i = 0; i < 4; i++)
#pragma unroll
        for (int r = 0; r < 4; r++) sc_[i][r] = 0.0f;

#pragma unroll
    for (int k0 = 0; k0 < 32; k0 += 8) {
        uint32_t a0, a1, a2, a3;
        ldsm4(a0, a1, a2, a3, qrow + k0 * 4 + akoff);
        uint32_t t0, t1, t2, t3;
        ldsm4(t0, t1, t2, t3, krow0 + k0 * 4 + bkoff);
        mma_tf32(sc_[0], a0, a1, a2, a3, t0, t1);
        mma_tf32(sc_[1], a0, a1, a2, a3, t2, t3);
        ldsm4(t0, t1, t2, t3, krow1 + k0 * 4 + bkoff);
        mma_tf32(sc_[2], a0, a1, a2, a3, t0, t1);
        mma_tf32(sc_[3], a0, a1, a2, a3, t2, t3);
    }

#pragma unroll
    for (int tn = 0; tn < 4; tn++) {
#pragma unroll
        for (int half = 0; half < 2; half++) {
            const int m = wm + rA + half * 8;
            const int n = wn + tn * 8 + cA * 2;
            *(float2*)&Ss[m][n] = make_float2(sc_[tn][half * 2 + 0] + bzv[tn][half].x,
                                              sc_[tn][half * 2 + 1] + bzv[tn][half].y);
        }
    }
    __syncthreads();

    // softmax without max-subtraction (scores bounded; exp safe in fp32)
#pragma unroll
    for (int r = warp * 8; r < warp * 8 + 8; ++r) {
        float e0 = __expf(Ss[r][lane]);
        float e1 = __expf(Ss[r][lane + 32]);
        float sm = e0 + e1;
#pragma unroll
        for (int o = 16; o; o >>= 1)
            sm += __shfl_xor_sync(0xffffffffu, sm, o);
        float inv = 1.0f / sm;
        Ss[r][lane]      = tf32r(e0 * inv);
        Ss[r][lane + 32] = tf32r(e1 * inv);
    }
    CP_WAIT(0);            // V resident
    __syncthreads();

    // O = P V
    const int wn2 = (warp & 1) * 16;
    float oc[2][4];
#pragma unroll
    for (int i = 0; i < 2; i++)
#pragma unroll
        for (int r = 0; r < 4; r++) oc[i][r] = 0.0f;

#pragma unroll
    for (int k0 = 0; k0 < 64; k0 += 8) {
        uint32_t a0, a1, a2, a3;
        ldsm4(a0, a1, a2, a3, srow + k0 * 4 + akoff);
#pragma unroll
        for (int tn = 0; tn < 2; tn++) {
            const int dc = wn2 + tn * 8 + rA;
            uint32_t b0 = __float_as_uint(Vs[k0 + cA][dc]);
            uint32_t b1 = __float_as_uint(Vs[k0 + 4 + cA][dc]);
            mma_tf32(oc[tn], a0, a1, a2, a3, b0, b1);
        }
    }

    const int b = bh / NH;
#pragma unroll
    for (int tn = 0; tn < 2; tn++) {
#pragma unroll
        for (int half = 0; half < 2; half++) {
            const int t = wm + rA + half * 8;
            const int d = wn2 + tn * 8 + cA * 2;
            // fp16 for the fp16 proj GEMM
            __half2 hw = __floats2half2_rn(oc[tn][half * 2 + 0],
                                           oc[tn][half * 2 + 1]);
            *(__half2*)&g_atth[((size_t)(b * NT + t)) * NC + h * ND + d] = hw;
        }
    }
}

// ---------------------------------------------------------------------------
// Launch  (order arranged so launch #4 = h16_gemm<0> for ncu capture)
// ---------------------------------------------------------------------------
extern "C" void kernel_launch(void* const* d_in, const int* in_sizes, int n_in,
                              void* d_out, int out_size) {
    const float* x      = (const float*)d_in[0];
    const float* qkv_w  = (const float*)d_in[1];
    const float* qkv_b  = (const float*)d_in[2];
    const float* proj_w = (const float*)d_in[3];
    const float* proj_b = (const float*)d_in[4];
    const float* rpb    = (const float*)d_in[5];
    const int*   rpi    = (const int*)d_in[6];
    float* out = (float*)d_out;

    cudaFuncSetAttribute(h16_gemm<0>, cudaFuncAttributeMaxDynamicSharedMemorySize, SMH);
    cudaFuncSetAttribute(h16_gemm<1>, cudaFuncAttributeMaxDynamicSharedMemorySize, SMH);

    __half *xh, *qwh, *pwh, *atth;
    cudaGetSymbolAddress((void**)&xh,   g_xh);
    cudaGetSymbolAddress((void**)&qwh,  g_qwh);
    cudaGetSymbolAddress((void**)&pwh,  g_pwh);
    cudaGetSymbolAddress((void**)&atth, g_atth);

    // fp16 conversions (launches 1-3)
    {
        int n4 = (MT * NC) / 4;
        tohalf_kernel<<<(n4 + 255) / 256, 256>>>(x, xh, n4);
        n4 = (N3C * NC) / 4;
        tohalf_kernel<<<(n4 + 255) / 256, 256>>>(qkv_w, qwh, n4);
        n4 = (NC * NC) / 4;
        tohalf_kernel<<<(n4 + 255) / 256, 256>>>(proj_w, pwh, n4);
    }

    // launch 4: the big QKV GEMM (profiled slot)
    dim3 g1(N3C / 128, MT / 128);   // (9, 1024)
    h16_gemm<0><<<g1, 256, SMH>>>(xh, qwh, qkv_b, nullptr);

    // launch 5: bias gather
    bias_kernel<<<(NH * NT * NT + 255) / 256, 256>>>(rpb, rpi);

    // launch 6: attention
    attn_kernel<<<NB * NH, 256>>>();

    // launch 7: projection GEMM
    dim3 g2(NC / 128, MT / 128);    // (3, 1024)
    h16_gemm<1><<<g2, 256, SMH>>>(atth, pwh, proj_b, out);
}

// round 15
// speedup vs baseline: 1.8958x; 1.1190x over previous
#include <cuda_runtime.h>
#include <cuda_fp16.h>
#include <cstdint>

// Problem constants
#define NB 2048
#define NT 64
#define NC 384
#define NH 12
#define ND 32
#define N3C 1152
#define MT 131072            // NB*NT rows
#define KDIM 384
#define SQ 50331648ull       // NB*NH*NT*ND

// ---------------- device scratch (no allocation allowed) -------------------
__device__ __half g_qkvh[3 * SQ];                   // (3,B,H,T,D) fp16
__device__ float g_bias[NH * NT * NT];              // (H,T,T)
__device__ __half g_xh[(size_t)MT * NC];            // fp16 x
__device__ __half g_qwh[(size_t)N3C * NC];          // fp16 qkv_w
__device__ __half g_pwh[(size_t)NC * NC];           // fp16 proj_w
__device__ __half g_atth[(size_t)MT * NC];          // attn output (fp16)

// ---------------- helpers ---------------------------------------------------
__device__ __forceinline__ uint32_t smem_u32(const void* p) {
    uint32_t a;
    asm("{ .reg .u64 t; cvta.to.shared.u64 t, %1; cvt.u32.u64 %0, t; }"
        : "=r"(a) : "l"(p));
    return a;
}

#define CP_ASYNC16(dst, src) \
    asm volatile("cp.async.cg.shared.global [%0], [%1], 16;" \
                 :: "r"(dst), "l"(src) : "memory")
#define CP_COMMIT() asm volatile("cp.async.commit_group;" ::: "memory")
#define CP_WAIT(n)  asm volatile("cp.async.wait_group %0;" :: "n"(n) : "memory")

__device__ __forceinline__ void ldsm4(uint32_t& r0, uint32_t& r1,
                                      uint32_t& r2, uint32_t& r3, uint32_t a) {
    asm volatile("ldmatrix.sync.aligned.m8n8.x4.shared.b16 {%0,%1,%2,%3}, [%4];"
                 : "=r"(r0), "=r"(r1), "=r"(r2), "=r"(r3) : "r"(a));
}
__device__ __forceinline__ void ldsm4t(uint32_t& r0, uint32_t& r1,
                                       uint32_t& r2, uint32_t& r3, uint32_t a) {
    asm volatile("ldmatrix.sync.aligned.m8n8.x4.trans.shared.b16 {%0,%1,%2,%3}, [%4];"
                 : "=r"(r0), "=r"(r1), "=r"(r2), "=r"(r3) : "r"(a));
}

__device__ __forceinline__ void mma_f16(float c[4], const uint32_t a[4],
                                        const uint32_t b[2]) {
    asm volatile(
        "mma.sync.aligned.m16n8k16.row.col.f32.f16.f16.f32 "
        "{%0,%1,%2,%3},{%4,%5,%6,%7},{%8,%9},{%0,%1,%2,%3};"
        : "+f"(c[0]), "+f"(c[1]), "+f"(c[2]), "+f"(c[3])
        : "r"(a[0]), "r"(a[1]), "r"(a[2]), "r"(a[3]), "r"(b[0]), "r"(b[1]));
}

// ---------------------------------------------------------------------------
// fp32 -> fp16 conversion pass
// ---------------------------------------------------------------------------
__global__ void tohalf_kernel(const float* __restrict__ src,
                              __half* __restrict__ dst, int n4) {
    int i = blockIdx.x * 256 + threadIdx.x;
    if (i >= n4) return;
    float4 v = ((const float4*)src)[i];
    ((__half2*)dst)[2 * i]     = __floats2half2_rn(v.x, v.y);
    ((__half2*)dst)[2 * i + 1] = __floats2half2_rn(v.z, v.w);
}

// ---------------------------------------------------------------------------
// Bias gather
// ---------------------------------------------------------------------------
__global__ void bias_kernel(const float* __restrict__ rpb,
                            const int* __restrict__ rpi) {
    int i = blockIdx.x * 256 + threadIdx.x;
    if (i >= NH * NT * NT) return;
    int h  = i / (NT * NT);
    int qk = i - h * (NT * NT);
    g_bias[i] = rpb[rpi[qk] * NH + h];
}

// ---------------------------------------------------------------------------
// Single-pass FP16 HMMA GEMM (R14 version; EPI==0 now writes fp16 q/k/v)
// ---------------------------------------------------------------------------
#define HSTG 32768               // A 16KB + W 16KB per stage
#define SMH (3 * HSTG)           // 96 KB

template <int EPI>
__global__ void __launch_bounds__(256, 2)
h16_gemm(const __half* __restrict__ A, const __half* __restrict__ W,
         const float* __restrict__ bias, float* __restrict__ out) {
    extern __shared__ char smem[];
    const uint32_t sb = smem_u32(smem);

    const int tid  = threadIdx.x;
    const int warp = tid >> 5;
    const int lane = tid & 31;
    const int m0 = blockIdx.y * 128;
    const int n0 = blockIdx.x * 128;

    const int wm = (warp >> 2) * 64;    // 0 or 64
    const int wn = (warp & 3) * 32;     // 0,32,64,96

    const int lrow = tid >> 1;
    const int lcb  = (tid & 1) * 4;
    const __half* Ap = A + (size_t)(m0 + lrow) * KDIM + lcb * 8;
    const __half* Wp = W + (size_t)(n0 + lrow) * KDIM + lcb * 8;
    const uint32_t lbase = lrow * 128;
    const int lsw = lrow & 7;

    auto fill = [&](int kc, int s) {
        const uint32_t base = sb + s * HSTG;
#pragma unroll
        for (int c = 0; c < 4; c++) {
            const uint32_t off = lbase + (((uint32_t)((lcb + c) ^ lsw)) << 4);
            CP_ASYNC16(base + off,         Ap + kc * 64 + c * 8);
            CP_ASYNC16(base + 16384 + off, Wp + kc * 64 + c * 8);
        }
    };

    float acc[4][4][4];
#pragma unroll
    for (int i = 0; i < 4; i++)
#pragma unroll
        for (int j = 0; j < 4; j++)
#pragma unroll
            for (int r = 0; r < 4; r++) acc[i][j][r] = 0.0f;

    const int mat = lane >> 3;      // 0..3
    const int mr  = lane & 7;       // 0..7

    fill(0, 0); CP_COMMIT();
    fill(1, 1); CP_COMMIT();

    int scur = 0;
    int snxt = 2;
    for (int kc = 0; kc < 6; ++kc) {
        if (kc + 2 < 6) { CP_WAIT(1); } else { CP_WAIT(0); }
        __syncthreads();
        if (kc + 2 < 6) {
            fill(kc + 2, snxt);
            CP_COMMIT();
        }

        const uint32_t smA = sb + scur * HSTG;
        const uint32_t smW = smA + 16384;
        scur = (scur + 1 == 3) ? 0 : scur + 1;
        snxt = (snxt + 1 == 3) ? 0 : snxt + 1;

#pragma unroll
        for (int kg = 0; kg < 4; kg++) {   // 4 x k16 per BK=64
            uint32_t af[4][4];
            const uint32_t achunk = ((uint32_t)(kg * 2 + (mat >> 1)) ^ (uint32_t)mr) << 4;
            const uint32_t arow   = wm + ((mat & 1) << 3) + mr;
#pragma unroll
            for (int tm = 0; tm < 4; tm++) {
                const uint32_t ad = smA + (arow + tm * 16) * 128 + achunk;
                ldsm4(af[tm][0], af[tm][1], af[tm][2], af[tm][3], ad);
            }
            uint32_t bf[4][2];
            const uint32_t bchunk = ((uint32_t)(kg * 2 + (mat & 1)) ^ (uint32_t)mr) << 4;
#pragma unroll
            for (int p = 0; p < 2; p++) {
                const uint32_t brow = wn + (2 * p + (mat >> 1)) * 8 + mr;
                const uint32_t bd = smW + brow * 128 + bchunk;
                uint32_t t0, t1, t2, t3;
                ldsm4(t0, t1, t2, t3, bd);
                bf[2 * p][0] = t0; bf[2 * p][1] = t1;
                bf[2 * p + 1][0] = t2; bf[2 * p + 1][1] = t3;
            }
#pragma unroll
            for (int tm = 0; tm < 4; tm++)
#pragma unroll
                for (int tn = 0; tn < 4; tn++)
                    mma_f16(acc[tm][tn], af[tm], bf[tn]);
        }
    }

    const int rA = lane >> 2;
    const int cA = lane & 3;
#pragma unroll
    for (int tm = 0; tm < 4; tm++) {
#pragma unroll
        for (int tn = 0; tn < 4; tn++) {
#pragma unroll
            for (int half = 0; half < 2; half++) {
                const int m = m0 + wm + tm * 16 + rA + half * 8;
                const int n = n0 + wn + tn * 8 + cA * 2;
                float v0 = acc[tm][tn][half * 2 + 0] + bias[n];
                float v1 = acc[tm][tn][half * 2 + 1] + bias[n + 1];
                if (EPI == 0) {
                    const int s   = n / NC;
                    const int rem = n - s * NC;
                    const int h   = rem >> 5;
                    const int d0  = rem & 31;
                    if (s == 0) {
                        const float sc = 0.17677669529663687f;  // 1/sqrt(32)
                        v0 *= sc; v1 *= sc;
                    }
                    const int b = m >> 6;
                    const int t = m & 63;
                    __half* dst = g_qkvh + (size_t)s * SQ +
                                  (((size_t)(b * NH + h)) * NT + t) * ND + d0;
                    *(__half2*)dst = __floats2half2_rn(v0, v1);
                } else {
                    *(float2*)(out + (size_t)m * NC + n) = make_float2(v0, v1);
                }
            }
        }
    }
}

// ---------------------------------------------------------------------------
// Attention: one CTA per (b,h). FP16 end-to-end mma (fp32 scores/softmax).
// Tiles fp16, pitch 40 halfs (80B, odd x16 => conflict-free ldmatrix).
// QK^T: A/B non-trans ldsm. PV: V via ldmatrix.trans from [t][d] layout.
// P stored fp16, unioned over dead Q tile. smem 36KB -> 6 CTAs/SM.
// ---------------------------------------------------------------------------
struct AttnSmem {
    __half Kh[64][40];                       // 5120 B
    __half Vh[64][40];                       // 5120 B
    union {
        __half Qh[64][40];                   // 5120 B (dead after QK)
        __half Ph[64][72];                   // 9216 B (pitch 144B, odd x16)
    } u;
    float Ss[64][68];                        // 17408 B
};

__global__ void __launch_bounds__(256) attn_kernel() {
    __shared__ __align__(16) AttnSmem S;

    const int bh  = blockIdx.x;
    const int h   = bh % NH;
    const int tid = threadIdx.x;

    const __half* Qg = g_qkvh + (size_t)bh * NT * ND;
    const __half* Kg = g_qkvh + SQ + (size_t)bh * NT * ND;
    const __half* Vg = g_qkvh + 2 * SQ + (size_t)bh * NT * ND;

    const uint32_t sK = smem_u32(&S.Kh[0][0]);
    const uint32_t sV = smem_u32(&S.Vh[0][0]);
    const uint32_t sQ = smem_u32(&S.u.Qh[0][0]);
    const uint32_t sP = smem_u32(&S.u.Ph[0][0]);

    // 256 16B-chunks per tensor; 1 per thread. Global row = 64B (32 halfs).
    {
        const int row = tid >> 2;
        const int cb  = tid & 3;
        const uint32_t soff = row * 80 + cb * 16;
        const size_t goff = (size_t)row * 32 + cb * 8;
        CP_ASYNC16(sK + soff, Kg + goff);
        CP_ASYNC16(sQ + soff, Qg + goff);
        CP_COMMIT();                      // group 1: K + Q
        CP_ASYNC16(sV + soff, Vg + goff);
        CP_COMMIT();                      // group 2: V
    }

    const int lane = tid & 31;
    const int warp = tid >> 5;
    const int rA = lane >> 2;
    const int cA = lane & 3;
    const int wm = (warp >> 1) * 16;
    const int wn = (warp & 1) * 32;
    const int mat = lane >> 3;
    const int mr  = lane & 7;

    // fragment addressing
    const uint32_t qrow = sQ + (uint32_t)(wm + ((mat & 1) << 3) + mr) * 80;
    const uint32_t prow = sP + (uint32_t)(wm + ((mat & 1) << 3) + mr) * 144;
    const uint32_t aoff = ((uint32_t)(mat >> 1)) << 4;   // k-half select (A)
    const uint32_t boff = ((uint32_t)(mat & 1)) << 4;    // k-half select (B)

    // prefetch bias to registers (L2 loads overlap QK^T)
    const float* bp = g_bias + h * NT * NT;
    float2 bzv[4][2];
#pragma unroll
    for (int tn = 0; tn < 4; tn++)
#pragma unroll
        for (int half = 0; half < 2; half++) {
            const int m = wm + rA + half * 8;
            const int n = wn + tn * 8 + cA * 2;
            bzv[tn][half] = *(const float2*)(bp + m * NT + n);
        }

    CP_WAIT(1);            // K, Q resident (V may still be in flight)
    __syncthreads();

    // S = Q K^T : 2 k16 steps, fp16 mma
    float sc_[4][4];
#pragma unroll
    for (int i = 0; i < 4; i++)
#pragma unroll
        for (int r = 0; r < 4; r++) sc_[i][r] = 0.0f;

#pragma unroll
    for (int ks = 0; ks < 2; ks++) {
        uint32_t a[4];
        ldsm4(a[0], a[1], a[2], a[3], qrow + ks * 32 + aoff);
#pragma unroll
        for (int p = 0; p < 2; p++) {
            const uint32_t brow = sK +
                (uint32_t)(wn + (2 * p + (mat >> 1)) * 8 + mr) * 80;
            uint32_t t0, t1, t2, t3;
            ldsm4(t0, t1, t2, t3, brow + ks * 32 + boff);
            uint32_t b0[2] = {t0, t1}, b1[2] = {t2, t3};
            mma_f16(sc_[2 * p],     a, b0);
            mma_f16(sc_[2 * p + 1], a, b1);
        }
    }

#pragma unroll
    for (int tn = 0; tn < 4; tn++) {
#pragma unroll
        for (int half = 0; half < 2; half++) {
            const int m = wm + rA + half * 8;
            const int n = wn + tn * 8 + cA * 2;
            *(float2*)&S.Ss[m][n] = make_float2(sc_[tn][half * 2 + 0] + bzv[tn][half].x,
                                                sc_[tn][half * 2 + 1] + bzv[tn][half].y);
        }
    }
    __syncthreads();       // Q dead after this point; Ph may overwrite

    // softmax without max-subtraction (scores bounded; exp safe in fp32)
#pragma unroll
    for (int r = warp * 8; r < warp * 8 + 8; ++r) {
        float e0 = __expf(S.Ss[r][lane]);
        float e1 = __expf(S.Ss[r][lane + 32]);
        float sm = e0 + e1;
#pragma unroll
        for (int o = 16; o; o >>= 1)
            sm += __shfl_xor_sync(0xffffffffu, sm, o);
        float inv = 1.0f / sm;
        S.u.Ph[r][lane]      = __float2half_rn(e0 * inv);
        S.u.Ph[r][lane + 32] = __float2half_rn(e1 * inv);
    }
    CP_WAIT(0);            // V resident
    __syncthreads();

    // O = P V : 4 k16 steps; P non-trans, V via ldmatrix.trans
    const int wn2 = (warp & 1) * 16;
    float oc[2][4];
#pragma unroll
    for (int i = 0; i < 2; i++)
#pragma unroll
        for (int r = 0; r < 4; r++) oc[i][r] = 0.0f;

#pragma unroll
    for (int ks = 0; ks < 4; ks++) {
        uint32_t a[4];
        ldsm4(a[0], a[1], a[2], a[3], prow + ks * 32 + aoff);
        // B: stored V rows t = ks*16 + (mat&1)*8 + mr, cols d = wn2 + (mat>>1)*8
        uint32_t t0, t1, t2, t3;
        const uint32_t vb = sV +
            (uint32_t)(ks * 16 + ((mat & 1) << 3) + mr) * 80 +
            (uint32_t)(wn2 + ((mat >> 1) << 3)) * 2;
        ldsm4t(t0, t1, t2, t3, vb);
        uint32_t b0[2] = {t0, t1}, b1[2] = {t2, t3};
        mma_f16(oc[0], a, b0);
        mma_f16(oc[1], a, b1);
    }

    const int b = bh / NH;
#pragma unroll
    for (int tn = 0; tn < 2; tn++) {
#pragma unroll
        for (int half = 0; half < 2; half++) {
            const int t = wm + rA + half * 8;
            const int d = wn2 + tn * 8 + cA * 2;
            __half2 hw = __floats2half2_rn(oc[tn][half * 2 + 0],
                                           oc[tn][half * 2 + 1]);
            *(__half2*)&g_atth[((size_t)(b * NT + t)) * NC + h * ND + d] = hw;
        }
    }
}

// ---------------------------------------------------------------------------
// Launch  (order arranged so launch #4 = h16_gemm<0> for ncu capture)
// ---------------------------------------------------------------------------
extern "C" void kernel_launch(void* const* d_in, const int* in_sizes, int n_in,
                              void* d_out, int out_size) {
    const float* x      = (const float*)d_in[0];
    const float* qkv_w  = (const float*)d_in[1];
    const float* qkv_b  = (const float*)d_in[2];
    const float* proj_w = (const float*)d_in[3];
    const float* proj_b = (const float*)d_in[4];
    const float* rpb    = (const float*)d_in[5];
    const int*   rpi    = (const int*)d_in[6];
    float* out = (float*)d_out;

    cudaFuncSetAttribute(h16_gemm<0>, cudaFuncAttributeMaxDynamicSharedMemorySize, SMH);
    cudaFuncSetAttribute(h16_gemm<1>, cudaFuncAttributeMaxDynamicSharedMemorySize, SMH);

    __half *xh, *qwh, *pwh, *atth;
    cudaGetSymbolAddress((void**)&xh,   g_xh);
    cudaGetSymbolAddress((void**)&qwh,  g_qwh);
    cudaGetSymbolAddress((void**)&pwh,  g_pwh);
    cudaGetSymbolAddress((void**)&atth, g_atth);

    // fp16 conversions (launches 1-3)
    {
        int n4 = (MT * NC) / 4;
        tohalf_kernel<<<(n4 + 255) / 256, 256>>>(x, xh, n4);
        n4 = (N3C * NC) / 4;
        tohalf_kernel<<<(n4 + 255) / 256, 256>>>(qkv_w, qwh, n4);
        n4 = (NC * NC) / 4;
        tohalf_kernel<<<(n4 + 255) / 256, 256>>>(proj_w, pwh, n4);
    }

    // launch 4: the big QKV GEMM (profiled slot)
    dim3 g1(N3C / 128, MT / 128);   // (9, 1024)
    h16_gemm<0><<<g1, 256, SMH>>>(xh, qwh, qkv_b, nullptr);

    // launch 5: bias gather
    bias_kernel<<<(NH * NT * NT + 255) / 256, 256>>>(rpb, rpi);

    // launch 6: attention
    attn_kernel<<<NB * NH, 256>>>();

    // launch 7: projection GEMM
    dim3 g2(NC / 128, MT / 128);    // (3, 1024)
    h16_gemm<1><<<g2, 256, SMH>>>(atth, pwh, proj_b, out);
}

// round 16
// speedup vs baseline: 1.9137x; 1.0094x over previous
#include <cuda_runtime.h>
#include <cuda_fp16.h>
#include <cstdint>

// Problem constants
#define NB 2048
#define NT 64
#define NC 384
#define NH 12
#define ND 32
#define N3C 1152
#define MT 131072            // NB*NT rows
#define KDIM 384
#define SQ 50331648ull       // NB*NH*NT*ND
#define NTILES (NB * NH)     // 24576 attention tiles

// ---------------- device scratch (no allocation allowed) -------------------
__device__ __half g_qkvh[3 * SQ];                   // (3,B,H,T,D) fp16
__device__ float g_bias[NH * NT * NT];              // (H,T,T)
__device__ __half g_xh[(size_t)MT * NC];            // fp16 x
__device__ __half g_qwh[(size_t)N3C * NC];          // fp16 qkv_w
__device__ __half g_pwh[(size_t)NC * NC];           // fp16 proj_w
__device__ __half g_atth[(size_t)MT * NC];          // attn output (fp16)

// ---------------- helpers ---------------------------------------------------
__device__ __forceinline__ uint32_t smem_u32(const void* p) {
    uint32_t a;
    asm("{ .reg .u64 t; cvta.to.shared.u64 t, %1; cvt.u32.u64 %0, t; }"
        : "=r"(a) : "l"(p));
    return a;
}

#define CP_ASYNC16(dst, src) \
    asm volatile("cp.async.cg.shared.global [%0], [%1], 16;" \
                 :: "r"(dst), "l"(src) : "memory")
#define CP_COMMIT() asm volatile("cp.async.commit_group;" ::: "memory")
#define CP_WAIT(n)  asm volatile("cp.async.wait_group %0;" :: "n"(n) : "memory")

__device__ __forceinline__ void ldsm4(uint32_t& r0, uint32_t& r1,
                                      uint32_t& r2, uint32_t& r3, uint32_t a) {
    asm volatile("ldmatrix.sync.aligned.m8n8.x4.shared.b16 {%0,%1,%2,%3}, [%4];"
                 : "=r"(r0), "=r"(r1), "=r"(r2), "=r"(r3) : "r"(a));
}
__device__ __forceinline__ void ldsm4t(uint32_t& r0, uint32_t& r1,
                                       uint32_t& r2, uint32_t& r3, uint32_t a) {
    asm volatile("ldmatrix.sync.aligned.m8n8.x4.trans.shared.b16 {%0,%1,%2,%3}, [%4];"
                 : "=r"(r0), "=r"(r1), "=r"(r2), "=r"(r3) : "r"(a));
}

__device__ __forceinline__ void mma_f16(float c[4], const uint32_t a[4],
                                        const uint32_t b[2]) {
    asm volatile(
        "mma.sync.aligned.m16n8k16.row.col.f32.f16.f16.f32 "
        "{%0,%1,%2,%3},{%4,%5,%6,%7},{%8,%9},{%0,%1,%2,%3};"
        : "+f"(c[0]), "+f"(c[1]), "+f"(c[2]), "+f"(c[3])
        : "r"(a[0]), "r"(a[1]), "r"(a[2]), "r"(a[3]), "r"(b[0]), "r"(b[1]));
}

// ---------------------------------------------------------------------------
// fp32 -> fp16 conversion pass
// ---------------------------------------------------------------------------
__global__ void tohalf_kernel(const float* __restrict__ src,
                              __half* __restrict__ dst, int n4) {
    int i = blockIdx.x * 256 + threadIdx.x;
    if (i >= n4) return;
    float4 v = ((const float4*)src)[i];
    ((__half2*)dst)[2 * i]     = __floats2half2_rn(v.x, v.y);
    ((__half2*)dst)[2 * i + 1] = __floats2half2_rn(v.z, v.w);
}

// ---------------------------------------------------------------------------
// Bias gather
// ---------------------------------------------------------------------------
__global__ void bias_kernel(const float* __restrict__ rpb,
                            const int* __restrict__ rpi) {
    int i = blockIdx.x * 256 + threadIdx.x;
    if (i >= NH * NT * NT) return;
    int h  = i / (NT * NT);
    int qk = i - h * (NT * NT);
    g_bias[i] = rpb[rpi[qk] * NH + h];
}

// ---------------------------------------------------------------------------
// Single-pass FP16 HMMA GEMM (R15 version — unchanged)
// ---------------------------------------------------------------------------
#define HSTG 32768               // A 16KB + W 16KB per stage
#define SMH (3 * HSTG)           // 96 KB

template <int EPI>
__global__ void __launch_bounds__(256, 2)
h16_gemm(const __half* __restrict__ A, const __half* __restrict__ W,
         const float* __restrict__ bias, float* __restrict__ out) {
    extern __shared__ char smem[];
    const uint32_t sb = smem_u32(smem);

    const int tid  = threadIdx.x;
    const int warp = tid >> 5;
    const int lane = tid & 31;
    const int m0 = blockIdx.y * 128;
    const int n0 = blockIdx.x * 128;

    const int wm = (warp >> 2) * 64;    // 0 or 64
    const int wn = (warp & 3) * 32;     // 0,32,64,96

    const int lrow = tid >> 1;
    const int lcb  = (tid & 1) * 4;
    const __half* Ap = A + (size_t)(m0 + lrow) * KDIM + lcb * 8;
    const __half* Wp = W + (size_t)(n0 + lrow) * KDIM + lcb * 8;
    const uint32_t lbase = lrow * 128;
    const int lsw = lrow & 7;

    auto fill = [&](int kc, int s) {
        const uint32_t base = sb + s * HSTG;
#pragma unroll
        for (int c = 0; c < 4; c++) {
            const uint32_t off = lbase + (((uint32_t)((lcb + c) ^ lsw)) << 4);
            CP_ASYNC16(base + off,         Ap + kc * 64 + c * 8);
            CP_ASYNC16(base + 16384 + off, Wp + kc * 64 + c * 8);
        }
    };

    float acc[4][4][4];
#pragma unroll
    for (int i = 0; i < 4; i++)
#pragma unroll
        for (int j = 0; j < 4; j++)
#pragma unroll
            for (int r = 0; r < 4; r++) acc[i][j][r] = 0.0f;

    const int mat = lane >> 3;      // 0..3
    const int mr  = lane & 7;       // 0..7

    fill(0, 0); CP_COMMIT();
    fill(1, 1); CP_COMMIT();

    int scur = 0;
    int snxt = 2;
    for (int kc = 0; kc < 6; ++kc) {
        if (kc + 2 < 6) { CP_WAIT(1); } else { CP_WAIT(0); }
        __syncthreads();
        if (kc + 2 < 6) {
            fill(kc + 2, snxt);
            CP_COMMIT();
        }

        const uint32_t smA = sb + scur * HSTG;
        const uint32_t smW = smA + 16384;
        scur = (scur + 1 == 3) ? 0 : scur + 1;
        snxt = (snxt + 1 == 3) ? 0 : snxt + 1;

#pragma unroll
        for (int kg = 0; kg < 4; kg++) {   // 4 x k16 per BK=64
            uint32_t af[4][4];
            const uint32_t achunk = ((uint32_t)(kg * 2 + (mat >> 1)) ^ (uint32_t)mr) << 4;
            const uint32_t arow   = wm + ((mat & 1) << 3) + mr;
#pragma unroll
            for (int tm = 0; tm < 4; tm++) {
                const uint32_t ad = smA + (arow + tm * 16) * 128 + achunk;
                ldsm4(af[tm][0], af[tm][1], af[tm][2], af[tm][3], ad);
            }
            uint32_t bf[4][2];
            const uint32_t bchunk = ((uint32_t)(kg * 2 + (mat & 1)) ^ (uint32_t)mr) << 4;
#pragma unroll
            for (int p = 0; p < 2; p++) {
                const uint32_t brow = wn + (2 * p + (mat >> 1)) * 8 + mr;
                const uint32_t bd = smW + brow * 128 + bchunk;
                uint32_t t0, t1, t2, t3;
                ldsm4(t0, t1, t2, t3, bd);
                bf[2 * p][0] = t0; bf[2 * p][1] = t1;
                bf[2 * p + 1][0] = t2; bf[2 * p + 1][1] = t3;
            }
#pragma unroll
            for (int tm = 0; tm < 4; tm++)
#pragma unroll
                for (int tn = 0; tn < 4; tn++)
                    mma_f16(acc[tm][tn], af[tm], bf[tn]);
        }
    }

    const int rA = lane >> 2;
    const int cA = lane & 3;
#pragma unroll
    for (int tm = 0; tm < 4; tm++) {
#pragma unroll
        for (int tn = 0; tn < 4; tn++) {
#pragma unroll
            for (int half = 0; half < 2; half++) {
                const int m = m0 + wm + tm * 16 + rA + half * 8;
                const int n = n0 + wn + tn * 8 + cA * 2;
                float v0 = acc[tm][tn][half * 2 + 0] + bias[n];
                float v1 = acc[tm][tn][half * 2 + 1] + bias[n + 1];
                if (EPI == 0) {
                    const int s   = n / NC;
                    const int rem = n - s * NC;
                    const int h   = rem >> 5;
                    const int d0  = rem & 31;
                    if (s == 0) {
                        const float sc = 0.17677669529663687f;  // 1/sqrt(32)
                        v0 *= sc; v1 *= sc;
                    }
                    const int b = m >> 6;
                    const int t = m & 63;
                    __half* dst = g_qkvh + (size_t)s * SQ +
                                  (((size_t)(b * NH + h)) * NT + t) * ND + d0;
                    *(__half2*)dst = __floats2half2_rn(v0, v1);
                } else {
                    *(float2*)(out + (size_t)m * NC + n) = make_float2(v0, v1);
                }
            }
        }
    }
}

// ---------------------------------------------------------------------------
// PERSISTENT attention. Each CTA loops over (b,h) tiles with cross-tile
// cp.async prefetch (double-buffered Q/K/V stages). Compute per tile is the
// R15 fp16 path (bit-identical arithmetic).
// smem: stage[2] {K 5120 | Q 5120 | V 5120} + fp32 Ss.
//       P (fp16, pitch 144B) unions over current stage's dead K+Q region.
// ---------------------------------------------------------------------------
#define STAGE_BYTES 15360
#define OFF_K 0
#define OFF_Q 5120
#define OFF_V 10240
#define OFF_SS (2 * STAGE_BYTES)            // 30720
#define ATTN_SMEM (OFF_SS + 64 * 68 * 4)    // 48128

__global__ void __launch_bounds__(256) attn_kernel() {
    __shared__ __align__(16) char sm[ATTN_SMEM];
    const uint32_t sb = smem_u32(sm);
    float* Ssp = (float*)(sm + OFF_SS);     // [64][68]

    const int tid = threadIdx.x;
    const int lane = tid & 31;
    const int warp = tid >> 5;
    const int rA = lane >> 2;
    const int cA = lane & 3;
    const int wm = (warp >> 1) * 16;
    const int wn = (warp & 1) * 32;
    const int wn2 = (warp & 1) * 16;
    const int mat = lane >> 3;
    const int mr  = lane & 7;

    // loader mapping (one 16B chunk per tensor per thread)
    const int lrow = tid >> 2;
    const int lcb  = tid & 3;
    const uint32_t lsoff = lrow * 80 + lcb * 16;
    const size_t lgoff = (size_t)lrow * 32 + lcb * 8;

    auto prefetch = [&](int bh, int s) {
        const uint32_t base = sb + s * STAGE_BYTES;
        const size_t tb = (size_t)bh * NT * ND;
        CP_ASYNC16(base + OFF_K + lsoff, g_qkvh + SQ + tb + lgoff);
        CP_ASYNC16(base + OFF_Q + lsoff, g_qkvh + tb + lgoff);
        CP_ASYNC16(base + OFF_V + lsoff, g_qkvh + 2 * SQ + tb + lgoff);
    };

    const uint32_t aoff = ((uint32_t)(mat >> 1)) << 4;   // k-half select (A)
    const uint32_t boff = ((uint32_t)(mat & 1)) << 4;    // k-half select (B)

    int tile = blockIdx.x;
    if (tile >= NTILES) return;

    prefetch(tile, 0); CP_COMMIT();

    int s = 0;
    for (; tile < NTILES; tile += gridDim.x, s ^= 1) {
        const int nxt = tile + gridDim.x;
        const int h = tile % NH;
        const int b = tile / NH;

        __syncthreads();                       // prior tile done with stage s^1
        const bool has_nxt = (nxt < NTILES);
        if (has_nxt) { prefetch(nxt, s ^ 1); CP_COMMIT(); }

        // bias prefetch to registers (overlaps the wait + QK)
        const float* bp = g_bias + h * NT * NT;
        float2 bzv[4][2];
#pragma unroll
        for (int tn = 0; tn < 4; tn++)
#pragma unroll
            for (int half = 0; half < 2; half++) {
                const int m = wm + rA + half * 8;
                const int n = wn + tn * 8 + cA * 2;
                bzv[tn][half] = *(const float2*)(bp + m * NT + n);
            }

        if (has_nxt) { CP_WAIT(1); } else { CP_WAIT(0); }
        __syncthreads();                       // stage s resident

        const uint32_t stg = sb + s * STAGE_BYTES;
        const uint32_t sK = stg + OFF_K;
        const uint32_t sQ = stg + OFF_Q;
        const uint32_t sV = stg + OFF_V;
        const uint32_t sP = stg;               // P over dead K+Q (after QK)

        const uint32_t qrow = sQ + (uint32_t)(wm + ((mat & 1) << 3) + mr) * 80;
        const uint32_t prow = sP + (uint32_t)(wm + ((mat & 1) << 3) + mr) * 144;

        // S = Q K^T : 2 k16 steps
        float sc_[4][4];
#pragma unroll
        for (int i = 0; i < 4; i++)
#pragma unroll
            for (int r = 0; r < 4; r++) sc_[i][r] = 0.0f;

#pragma unroll
        for (int ks = 0; ks < 2; ks++) {
            uint32_t a[4];
            ldsm4(a[0], a[1], a[2], a[3], qrow + ks * 32 + aoff);
#pragma unroll
            for (int p = 0; p < 2; p++) {
                const uint32_t brow = sK +
                    (uint32_t)(wn + (2 * p + (mat >> 1)) * 8 + mr) * 80;
                uint32_t t0, t1, t2, t3;
                ldsm4(t0, t1, t2, t3, brow + ks * 32 + boff);
                uint32_t b0[2] = {t0, t1}, b1[2] = {t2, t3};
                mma_f16(sc_[2 * p],     a, b0);
                mma_f16(sc_[2 * p + 1], a, b1);
            }
        }

#pragma unroll
        for (int tn = 0; tn < 4; tn++) {
#pragma unroll
            for (int half = 0; half < 2; half++) {
                const int m = wm + rA + half * 8;
                const int n = wn + tn * 8 + cA * 2;
                *(float2*)&Ssp[m * 68 + n] =
                    make_float2(sc_[tn][half * 2 + 0] + bzv[tn][half].x,
                                sc_[tn][half * 2 + 1] + bzv[tn][half].y);
            }
        }
        __syncthreads();                       // K,Q dead; P may overwrite

        // softmax (no max-subtraction; scores bounded, fp32 exp safe)
#pragma unroll
        for (int r = warp * 8; r < warp * 8 + 8; ++r) {
            float e0 = __expf(Ssp[r * 68 + lane]);
            float e1 = __expf(Ssp[r * 68 + lane + 32]);
            float smv = e0 + e1;
#pragma unroll
            for (int o = 16; o; o >>= 1)
                smv += __shfl_xor_sync(0xffffffffu, smv, o);
            float inv = 1.0f / smv;
            __half* pr = (__half*)(sm + s * STAGE_BYTES) + r * 72;
            pr[lane]      = __float2half_rn(e0 * inv);
            pr[lane + 32] = __float2half_rn(e1 * inv);
        }
        __syncthreads();

        // O = P V : 4 k16 steps; P non-trans, V via ldmatrix.trans
        float oc[2][4];
#pragma unroll
        for (int i = 0; i < 2; i++)
#pragma unroll
            for (int r = 0; r < 4; r++) oc[i][r] = 0.0f;

#pragma unroll
        for (int ks = 0; ks < 4; ks++) {
            uint32_t a[4];
            ldsm4(a[0], a[1], a[2], a[3], prow + ks * 32 + aoff);
            uint32_t t0, t1, t2, t3;
            const uint32_t vb = sV +
                (uint32_t)(ks * 16 + ((mat & 1) << 3) + mr) * 80 +
                (uint32_t)(wn2 + ((mat >> 1) << 3)) * 2;
            ldsm4t(t0, t1, t2, t3, vb);
            uint32_t b0[2] = {t0, t1}, b1[2] = {t2, t3};
            mma_f16(oc[0], a, b0);
            mma_f16(oc[1], a, b1);
        }

#pragma unroll
        for (int tn = 0; tn < 2; tn++) {
#pragma unroll
            for (int half = 0; half < 2; half++) {
                const int t = wm + rA + half * 8;
                const int d = wn2 + tn * 8 + cA * 2;
                __half2 hw = __floats2half2_rn(oc[tn][half * 2 + 0],
                                               oc[tn][half * 2 + 1]);
                *(__half2*)&g_atth[((size_t)(b * NT + t)) * NC + h * ND + d] = hw;
            }
        }
    }
}

// ---------------------------------------------------------------------------
// Launch  (order arranged so launch #4 = h16_gemm<0> for ncu capture)
// ---------------------------------------------------------------------------
extern "C" void kernel_launch(void* const* d_in, const int* in_sizes, int n_in,
                              void* d_out, int out_size) {
    const float* x      = (const float*)d_in[0];
    const float* qkv_w  = (const float*)d_in[1];
    const float* qkv_b  = (const float*)d_in[2];
    const float* proj_w = (const float*)d_in[3];
    const float* proj_b = (const float*)d_in[4];
    const float* rpb    = (const float*)d_in[5];
    const int*   rpi    = (const int*)d_in[6];
    float* out = (float*)d_out;

    cudaFuncSetAttribute(h16_gemm<0>, cudaFuncAttributeMaxDynamicSharedMemorySize, SMH);
    cudaFuncSetAttribute(h16_gemm<1>, cudaFuncAttributeMaxDynamicSharedMemorySize, SMH);

    __half *xh, *qwh, *pwh, *atth;
    cudaGetSymbolAddress((void**)&xh,   g_xh);
    cudaGetSymbolAddress((void**)&qwh,  g_qwh);
    cudaGetSymbolAddress((void**)&pwh,  g_pwh);
    cudaGetSymbolAddress((void**)&atth, g_atth);

    // persistent attention grid: exactly one wave of resident CTAs
    int nsm = 148, occ = 4;
    cudaDeviceGetAttribute(&nsm, cudaDevAttrMultiProcessorCount, 0);
    cudaOccupancyMaxActiveBlocksPerMultiprocessor(&occ, attn_kernel, 256, 0);
    if (occ < 1) occ = 1;
    int attn_grid = nsm * occ;
    if (attn_grid > NTILES) attn_grid = NTILES;

    // fp16 conversions (launches 1-3)
    {
        int n4 = (MT * NC) / 4;
        tohalf_kernel<<<(n4 + 255) / 256, 256>>>(x, xh, n4);
        n4 = (N3C * NC) / 4;
        tohalf_kernel<<<(n4 + 255) / 256, 256>>>(qkv_w, qwh, n4);
        n4 = (NC * NC) / 4;
        tohalf_kernel<<<(n4 + 255) / 256, 256>>>(proj_w, pwh, n4);
    }

    // launch 4: the big QKV GEMM (profiled slot)
    dim3 g1(N3C / 128, MT / 128);   // (9, 1024)
    h16_gemm<0><<<g1, 256, SMH>>>(xh, qwh, qkv_b, nullptr);

    // launch 5: bias gather
    bias_kernel<<<(NH * NT * NT + 255) / 256, 256>>>(rpb, rpi);

    // launch 6: persistent attention
    attn_kernel<<<attn_grid, 256>>>();

    // launch 7: projection GEMM
    dim3 g2(NC / 128, MT / 128);    // (3, 1024)
    h16_gemm<1><<<g2, 256, SMH>>>(atth, pwh, proj_b, out);
}